// round 7
// baseline (speedup 1.0000x reference)
#include <cuda_runtime.h>
#include <math.h>

#define Bsz   4096
#define Lh    64
#define Dh    16
#define Hh    128
#define ROWS  32
#define THREADS 512
#define CTAS  128
#define HEAD_IN 144
#define OUTD  60
#define SQ    (Hh*Hh)
#define NPAIR (Hh/2)

typedef unsigned long long ull;

#define FMA2(acc, a, b) \
    asm("fma.rn.f32x2 %0, %1, %2, %3;" : "=l"(acc) : "l"(a), "l"(b), "l"(acc))
#define PACK2(d, lo, hi) \
    asm("mov.b64 %0, {%1, %2};" : "=l"(d) : "f"(lo), "f"(hi))

__device__ __forceinline__ float2 unpack2(ull v) {
    float2 r;
    asm("mov.b64 {%0, %1}, %2;" : "=f"(r.x), "=f"(r.y) : "l"(v));
    return r;
}

// pre-packed weights, k-contiguous for coalesced LDG.128:
// g_wg[l][pair][0][k]=(wi,wo)  [1][k]=(wc,ui)  [2][k]=(uo,uc)
__device__ ulonglong2 g_wg[2][NPAIR][3][Hh];
__device__ ull        g_wd[2][NPAIR][Hh];

__global__ void pack_kernel(const float* __restrict__ Wx,
                            const float* __restrict__ Uh,
                            const float* __restrict__ Wd)
{
    int idx = blockIdx.x * blockDim.x + threadIdx.x;
    if (idx >= 2 * NPAIR * Hh) return;
    int k = idx & (Hh - 1);
    int p = (idx >> 7) & (NPAIR - 1);
    int l = idx >> 13;
    int j0 = 2 * p, j1 = j0 + 1;

    const float* wx = Wx + (size_t)l * 4 * SQ;
    const float* uh = Uh + (size_t)l * 4 * SQ;

    ull wi, wo, wc, ui, uo, uc, wd;
    PACK2(wi, wx[1*SQ + j0*Hh + k], wx[1*SQ + j1*Hh + k]);
    PACK2(wo, wx[2*SQ + j0*Hh + k], wx[2*SQ + j1*Hh + k]);
    PACK2(wc, wx[3*SQ + j0*Hh + k], wx[3*SQ + j1*Hh + k]);
    PACK2(ui, uh[1*SQ + j0*Hh + k], uh[1*SQ + j1*Hh + k]);
    PACK2(uo, uh[2*SQ + j0*Hh + k], uh[2*SQ + j1*Hh + k]);
    PACK2(uc, uh[3*SQ + j0*Hh + k], uh[3*SQ + j1*Hh + k]);
    const float* wdm = Wd + (size_t)l * SQ;
    PACK2(wd, wdm[j0*Hh + k], wdm[j1*Hh + k]);

    ulonglong2 v;
    v.x = wi; v.y = wo; g_wg[l][p][0][k] = v;
    v.x = wc; v.y = ui; g_wg[l][p][1][k] = v;
    v.x = uo; v.y = uc; g_wg[l][p][2][k] = v;
    g_wd[l][p][k] = wd;
}

struct SM {
    float h[2][ROWS][Hh];
    float c[2][ROWS][Hh];
    float xin[ROWS][Hh];
    float ht[ROWS][Hh];
    float sv[ROWS][Hh];
    float wp[Dh][Hh];
    float histb[ROWS][Dh];
    float msk[ROWS];
    float dec[ROWS];
    int   last[ROWS];
};

__device__ __forceinline__ float tanh_f(float x) {
    float e = __expf(2.0f * x);
    return 1.0f - __fdividef(2.0f, e + 1.0f);
}
__device__ __forceinline__ float sig_f(float x) {
    return __fdividef(1.0f, 1.0f + __expf(-x));
}

__device__ __forceinline__ float fixv(float x) {
    if (!(x == x)) return 0.0f;
    if (x > 1e38f) return 1e4f;
    if (x < -1e38f) return -1e4f;
    return x;
}

__global__ void __launch_bounds__(THREADS, 1)
tlstm_kernel(const float* __restrict__ history, const float* __restrict__ hmask,
             const float* __restrict__ Wp,  const float* __restrict__ bp,
             const float* __restrict__ bx,  const float* __restrict__ bd,
             const float* __restrict__ Wt,  const float* __restrict__ bt,
             const float* __restrict__ ln_g, const float* __restrict__ ln_b,
             const float* __restrict__ W1,  const float* __restrict__ b1,
             const float* __restrict__ W2,  const float* __restrict__ b2,
             float* __restrict__ out)
{
    extern __shared__ char smraw[];
    SM* sm = reinterpret_cast<SM*>(smraw);

    const int tid  = threadIdx.x;
    const int b0   = blockIdx.x * ROWS;
    const int w    = tid >> 5;
    const int lane = tid & 31;
    const int wk   = w & 3;            // 4 warps along k
    const int wr   = w >> 2;           // 4 row groups
    const int half = lane >> 4;
    const int kk   = lane & 15;
    const int k0   = wk * 16 + kk;     // first output channel (0..63)
    const int k1   = k0 + 64;          // second output channel (64..127)
    const int rb   = wr * 8 + half * 4; // first of this thread's 4 rows

    for (int i = tid; i < 2 * ROWS * Hh; i += THREADS) {
        (&sm->h[0][0][0])[i] = 0.0f;
        (&sm->c[0][0][0])[i] = 0.0f;
    }
    for (int i = tid; i < Dh * Hh; i += THREADS)
        (&sm->wp[0][0])[i] = Wp[i];
    if (tid < ROWS) {
        const float* mp = hmask + (size_t)(b0 + tid) * Lh;
        float s = 0.0f;
        for (int t = 0; t < Lh; t++) s += mp[t];
        s = fminf(fmaxf(s, 1.0f), (float)Lh);
        sm->last[tid] = (int)s - 1;
    }
    __syncthreads();

    // per-thread constants for both k channels
    float bpk[2], bxi[2][2], bxo[2][2], bxc[2][2], bdl[2][2], wtl[2][2], btl[2][2];
    {
        int ks[2] = {k0, k1};
        #pragma unroll
        for (int q = 0; q < 2; q++) {
            int k = ks[q];
            bpk[q] = bp[k];
            bxi[0][q] = bx[1*Hh + k]; bxo[0][q] = bx[2*Hh + k]; bxc[0][q] = bx[3*Hh + k];
            bxi[1][q] = bx[5*Hh + k]; bxo[1][q] = bx[6*Hh + k]; bxc[1][q] = bx[7*Hh + k];
            bdl[0][q] = bd[k];        bdl[1][q] = bd[Hh + k];
            wtl[0][q] = Wt[k];        wtl[1][q] = Wt[Hh + k];
            btl[0][q] = bt[k];        btl[1][q] = bt[Hh + k];
        }
    }

    // ================= time loop =================
    for (int t = 0; t < Lh; t++) {
        {
            int r = tid >> 4, d = tid & 15;   // 512 threads = 32*16 exactly
            sm->histb[r][d] = history[((size_t)(b0 + r) * Lh + t) * Dh + d];
        }
        if (tid < ROWS)
            sm->msk[tid] = hmask[(size_t)(b0 + tid) * Lh + t];
        __syncthreads();

        if (tid < ROWS) {
            float dd = fmaxf(sm->histb[tid][5], 0.0f);
            sm->dec[tid] = 1.0f / logf(2.718281828459045f + dd);
        }
        // x_t = hist @ Wp + bp  (2 k channels x 4 rows)
        {
            float a0[4], a1[4];
            #pragma unroll
            for (int rr = 0; rr < 4; rr++) { a0[rr] = bpk[0]; a1[rr] = bpk[1]; }
            #pragma unroll
            for (int d = 0; d < Dh; d++) {
                float w0 = sm->wp[d][k0];
                float w1 = sm->wp[d][k1];
                #pragma unroll
                for (int rr = 0; rr < 4; rr++) {
                    float hv = sm->histb[rb + rr][d];
                    a0[rr] += hv * w0;
                    a1[rr] += hv * w1;
                }
            }
            #pragma unroll
            for (int rr = 0; rr < 4; rr++) {
                sm->xin[rb + rr][k0] = a0[rr];
                sm->xin[rb + rr][k1] = a1[rr];
            }
        }
        __syncthreads();

        #pragma unroll
        for (int l = 0; l < 2; l++) {
            const float* inp  = (l == 0) ? &sm->xin[0][0] : &sm->h[0][0][0];
            float*       hcur = &sm->h[l][0][0];

            // packed accumulators: 3 gates x 2 k x 4 rows = 24 ull (48 regs)
            ull zi2[8], zo2[8], zc2[8];
            #pragma unroll
            for (int q = 0; q < 2; q++) {
                #pragma unroll
                for (int rr = 0; rr < 4; rr++) {
                    PACK2(zi2[q*4+rr], bxi[l][q], 0.0f);
                    PACK2(zo2[q*4+rr], bxo[l][q], 0.0f);
                    PACK2(zc2[q*4+rr], bxc[l][q], 0.0f);
                }
            }

            const ulonglong2* __restrict__ pw = &g_wg[l][0][0][0];
            #pragma unroll 2
            for (int p = 0; p < NPAIR; p++) {
                ulonglong2 wa0 = pw[k0];          // (wi,wo) k0
                ulonglong2 wb0 = pw[Hh + k0];     // (wc,ui) k0
                ulonglong2 wc0 = pw[2*Hh + k0];   // (uo,uc) k0
                ulonglong2 wa1 = pw[k1];
                ulonglong2 wb1 = pw[Hh + k1];
                ulonglong2 wc1 = pw[2*Hh + k1];
                const int j = 2 * p;
                #pragma unroll
                for (int rr = 0; rr < 4; rr++) {
                    const int r = rb + rr;
                    ull xu = *reinterpret_cast<const ull*>(inp  + r*Hh + j);
                    ull hu = *reinterpret_cast<const ull*>(hcur + r*Hh + j);
                    FMA2(zi2[rr],   xu, wa0.x);
                    FMA2(zo2[rr],   xu, wa0.y);
                    FMA2(zc2[rr],   xu, wb0.x);
                    FMA2(zi2[rr],   hu, wb0.y);
                    FMA2(zo2[rr],   hu, wc0.x);
                    FMA2(zc2[rr],   hu, wc0.y);
                    FMA2(zi2[4+rr], xu, wa1.x);
                    FMA2(zo2[4+rr], xu, wa1.y);
                    FMA2(zc2[4+rr], xu, wb1.x);
                    FMA2(zi2[4+rr], hu, wb1.y);
                    FMA2(zo2[4+rr], hu, wc1.x);
                    FMA2(zc2[4+rr], hu, wc1.y);
                }
                pw += 3 * Hh;
            }

            float ot[8], htl[8];
            #pragma unroll
            for (int q = 0; q < 2; q++) {
                const int k = q ? k1 : k0;
                #pragma unroll
                for (int rr = 0; rr < 4; rr++) {
                    float2 a = unpack2(zi2[q*4+rr]);
                    float2 b = unpack2(zo2[q*4+rr]);
                    float2 c = unpack2(zc2[q*4+rr]);
                    float it = sig_f(a.x + a.y);
                    ot[q*4+rr]  = sig_f(b.x + b.y);
                    htl[q*4+rr] = tanh_f(c.x + c.y) + it;
                    sm->ht[rb + rr][k] = htl[q*4+rr];
                }
            }
            __syncthreads();

            // h_short = tanh(h_tilde @ Wd + bd)
            const ull* __restrict__ pd = &g_wd[l][0][0];
            ull hs2[8];
            #pragma unroll
            for (int q = 0; q < 2; q++)
                #pragma unroll
                for (int rr = 0; rr < 4; rr++)
                    PACK2(hs2[q*4+rr], bdl[l][q], 0.0f);
            #pragma unroll 4
            for (int p = 0; p < NPAIR; p++) {
                ull wd0 = pd[k0];
                ull wd1 = pd[k1];
                const int j = 2 * p;
                #pragma unroll
                for (int rr = 0; rr < 4; rr++) {
                    ull t2 = *reinterpret_cast<const ull*>(&sm->ht[rb + rr][j]);
                    FMA2(hs2[rr],   t2, wd0);
                    FMA2(hs2[4+rr], t2, wd1);
                }
                pd += Hh;
            }

            #pragma unroll
            for (int q = 0; q < 2; q++) {
                const int k = q ? k1 : k0;
                #pragma unroll
                for (int rr = 0; rr < 4; rr++) {
                    const int r = rb + rr;
                    float2 av   = unpack2(hs2[q*4+rr]);
                    float hs    = tanh_f(av.x + av.y);
                    float dt    = sig_f(sm->dec[r] * wtl[l][q] + btl[l][q]);
                    float hstar = (htl[q*4+rr] - hs) + hs * dt;
                    float cold  = sm->c[l][r][k];
                    float cn    = tanh_f(hstar + ot[q*4+rr] * cold);
                    float hn    = ot[q*4+rr] * tanh_f(cn);
                    float m     = sm->msk[r];
                    float hv    = m * hn + (1.0f - m) * hcur[r*Hh + k];
                    float cv    = m * cn + (1.0f - m) * cold;
                    sm->c[l][r][k] = cv;
                    hcur[r*Hh + k] = hv;
                    if (l == 1 && t == sm->last[r])
                        sm->sv[r][k] = m * hv;
                }
            }
            __syncthreads();
        }
    }

    // ================= forecast head =================
    {
        int r = tid >> 4, d = tid & 15;
        sm->histb[r][d] = history[((size_t)(b0 + r) * Lh + sm->last[r]) * Dh + d];
    }
    __syncthreads();

    const unsigned FULL = 0xffffffffu;
    #pragma unroll
    for (int rr = 0; rr < 2; rr++) {
        const int r = w * 2 + rr;

        float s = 0.0f, s2 = 0.0f;
        for (int i = lane; i < HEAD_IN; i += 32) {
            float v = (i < 16) ? sm->histb[r][i] : sm->sv[r][i - 16];
            s += v; s2 += v * v;
        }
        #pragma unroll
        for (int off = 16; off; off >>= 1) {
            s  += __shfl_xor_sync(FULL, s,  off);
            s2 += __shfl_xor_sync(FULL, s2, off);
        }
        float mean = s / (float)HEAD_IN;
        float var  = s2 / (float)HEAD_IN - mean * mean;
        float rstd = rsqrtf(var + 1e-5f);

        const int j0 = lane * 4;
        float4 acc = *reinterpret_cast<const float4*>(b1 + j0);
        for (int i = 0; i < HEAD_IN; i++) {
            float v  = (i < 16) ? sm->histb[r][i] : sm->sv[r][i - 16];
            float sn = (v - mean) * rstd * ln_g[i] + ln_b[i];
            float4 w4 = *reinterpret_cast<const float4*>(W1 + i * Hh + j0);
            acc.x += sn * w4.x; acc.y += sn * w4.y;
            acc.z += sn * w4.z; acc.w += sn * w4.w;
        }
        float y[4] = { fmaxf(acc.x, 0.0f), fmaxf(acc.y, 0.0f),
                       fmaxf(acc.z, 0.0f), fmaxf(acc.w, 0.0f) };

        const int o0 = lane, o1 = lane + 32;
        float a0 = b2[o0];
        float a1 = (o1 < OUTD) ? b2[o1] : 0.0f;
        #pragma unroll
        for (int q = 0; q < 4; q++) {
            float yq = y[q];
            #pragma unroll 8
            for (int src = 0; src < 32; src++) {
                float v = __shfl_sync(FULL, yq, src);
                int   j = src * 4 + q;
                a0 += v * W2[j * OUTD + o0];
                if (o1 < OUTD) a1 += v * W2[j * OUTD + o1];
            }
        }
        size_t ob = (size_t)(b0 + r) * OUTD;
        out[ob + o0] = fixv(a0);
        if (o1 < OUTD) out[ob + o1] = fixv(a1);
    }
}

extern "C" void kernel_launch(void* const* d_in, const int* in_sizes, int n_in,
                              void* d_out, int out_size)
{
    const float* history = (const float*)d_in[0];
    const float* hmask   = (const float*)d_in[1];
    const float* Wp      = (const float*)d_in[2];
    const float* bp      = (const float*)d_in[3];
    const float* Wx      = (const float*)d_in[4];
    const float* bx      = (const float*)d_in[5];
    const float* Uh      = (const float*)d_in[6];
    const float* Wd      = (const float*)d_in[7];
    const float* bd      = (const float*)d_in[8];
    const float* Wt      = (const float*)d_in[9];
    const float* bt      = (const float*)d_in[10];
    const float* ln_g    = (const float*)d_in[11];
    const float* ln_b    = (const float*)d_in[12];
    const float* W1      = (const float*)d_in[13];
    const float* b1      = (const float*)d_in[14];
    const float* W2      = (const float*)d_in[15];
    const float* b2      = (const float*)d_in[16];

    pack_kernel<<<(2 * NPAIR * Hh + 255) / 256, 256>>>(Wx, Uh, Wd);

    cudaFuncSetAttribute(tlstm_kernel,
                         cudaFuncAttributeMaxDynamicSharedMemorySize,
                         (int)sizeof(SM));
    tlstm_kernel<<<CTAS, THREADS, sizeof(SM)>>>(
        history, hmask, Wp, bp, bx, bd, Wt, bt,
        ln_g, ln_b, W1, b1, W2, b2, (float*)d_out);
}

// round 8
// speedup vs baseline: 1.0017x; 1.0017x over previous
#include <cuda_runtime.h>
#include <math.h>

#define Bsz   4096
#define Lh    64
#define Dh    16
#define Hh    128
#define ROWS  32
#define THREADS 512
#define CTAS  128
#define HEAD_IN 144
#define OUTD  60
#define SQ    (Hh*Hh)
#define NPAIR (Hh/2)

typedef unsigned long long ull;

#define FMA2(acc, a, b) \
    asm("fma.rn.f32x2 %0, %1, %2, %3;" : "=l"(acc) : "l"(a), "l"(b), "l"(acc))
#define PACK2(d, lo, hi) \
    asm("mov.b64 %0, {%1, %2};" : "=l"(d) : "f"(lo), "f"(hi))

__device__ __forceinline__ float2 unpack2(ull v) {
    float2 r;
    asm("mov.b64 {%0, %1}, %2;" : "=f"(r.x), "=f"(r.y) : "l"(v));
    return r;
}

// pre-packed weights, k-contiguous for coalesced LDG.128:
// g_wg[l][pair][0][k]=(wi,wo)  [1][k]=(wc,ui)  [2][k]=(uo,uc)
__device__ ulonglong2 g_wg[2][NPAIR][3][Hh];
__device__ ull        g_wd[2][NPAIR][Hh];

__global__ void pack_kernel(const float* __restrict__ Wx,
                            const float* __restrict__ Uh,
                            const float* __restrict__ Wd)
{
    int idx = blockIdx.x * blockDim.x + threadIdx.x;
    if (idx >= 2 * NPAIR * Hh) return;
    int k = idx & (Hh - 1);
    int p = (idx >> 7) & (NPAIR - 1);
    int l = idx >> 13;
    int j0 = 2 * p, j1 = j0 + 1;

    const float* wx = Wx + (size_t)l * 4 * SQ;
    const float* uh = Uh + (size_t)l * 4 * SQ;

    ull wi, wo, wc, ui, uo, uc, wd;
    PACK2(wi, wx[1*SQ + j0*Hh + k], wx[1*SQ + j1*Hh + k]);
    PACK2(wo, wx[2*SQ + j0*Hh + k], wx[2*SQ + j1*Hh + k]);
    PACK2(wc, wx[3*SQ + j0*Hh + k], wx[3*SQ + j1*Hh + k]);
    PACK2(ui, uh[1*SQ + j0*Hh + k], uh[1*SQ + j1*Hh + k]);
    PACK2(uo, uh[2*SQ + j0*Hh + k], uh[2*SQ + j1*Hh + k]);
    PACK2(uc, uh[3*SQ + j0*Hh + k], uh[3*SQ + j1*Hh + k]);
    const float* wdm = Wd + (size_t)l * SQ;
    PACK2(wd, wdm[j0*Hh + k], wdm[j1*Hh + k]);

    ulonglong2 v;
    v.x = wi; v.y = wo; g_wg[l][p][0][k] = v;
    v.x = wc; v.y = ui; g_wg[l][p][1][k] = v;
    v.x = uo; v.y = uc; g_wg[l][p][2][k] = v;
    g_wd[l][p][k] = wd;
}

struct SM {
    float h[2][ROWS][Hh];
    float c[2][ROWS][Hh];
    float xin[ROWS][Hh];
    float ht[ROWS][Hh];
    float sv[ROWS][Hh];
    float wp[Dh][Hh];
    float histb[ROWS][Dh];
    float msk[ROWS];
    float dec[ROWS];
    int   last[ROWS];
};

__device__ __forceinline__ float tanh_f(float x) {
    float e = __expf(2.0f * x);
    return 1.0f - __fdividef(2.0f, e + 1.0f);
}
__device__ __forceinline__ float sig_f(float x) {
    return __fdividef(1.0f, 1.0f + __expf(-x));
}

__device__ __forceinline__ float fixv(float x) {
    if (!(x == x)) return 0.0f;
    if (x > 1e38f) return 1e4f;
    if (x < -1e38f) return -1e4f;
    return x;
}

__global__ void __launch_bounds__(THREADS, 1)
tlstm_kernel(const float* __restrict__ history, const float* __restrict__ hmask,
             const float* __restrict__ Wp,  const float* __restrict__ bp,
             const float* __restrict__ bx,  const float* __restrict__ bd,
             const float* __restrict__ Wt,  const float* __restrict__ bt,
             const float* __restrict__ ln_g, const float* __restrict__ ln_b,
             const float* __restrict__ W1,  const float* __restrict__ b1,
             const float* __restrict__ W2,  const float* __restrict__ b2,
             float* __restrict__ out)
{
    extern __shared__ char smraw[];
    SM* sm = reinterpret_cast<SM*>(smraw);

    const int tid  = threadIdx.x;
    const int b0   = blockIdx.x * ROWS;
    const int w    = tid >> 5;
    const int lane = tid & 31;
    const int wk   = w & 3;            // 4 warps along k
    const int wr   = w >> 2;           // 4 row groups
    const int half = lane >> 4;
    const int kk   = lane & 15;
    const int k0   = wk * 16 + kk;     // first output channel (0..63)
    const int k1   = k0 + 64;          // second output channel (64..127)
    const int rb   = wr * 8 + half * 4; // first of this thread's 4 rows

    for (int i = tid; i < 2 * ROWS * Hh; i += THREADS) {
        (&sm->h[0][0][0])[i] = 0.0f;
        (&sm->c[0][0][0])[i] = 0.0f;
    }
    for (int i = tid; i < Dh * Hh; i += THREADS)
        (&sm->wp[0][0])[i] = Wp[i];
    if (tid < ROWS) {
        const float* mp = hmask + (size_t)(b0 + tid) * Lh;
        float s = 0.0f;
        for (int t = 0; t < Lh; t++) s += mp[t];
        s = fminf(fmaxf(s, 1.0f), (float)Lh);
        sm->last[tid] = (int)s - 1;
    }
    __syncthreads();

    // per-thread constants for both k channels
    float bpk[2], bxi[2][2], bxo[2][2], bxc[2][2], bdl[2][2], wtl[2][2], btl[2][2];
    {
        int ks[2] = {k0, k1};
        #pragma unroll
        for (int q = 0; q < 2; q++) {
            int k = ks[q];
            bpk[q] = bp[k];
            bxi[0][q] = bx[1*Hh + k]; bxo[0][q] = bx[2*Hh + k]; bxc[0][q] = bx[3*Hh + k];
            bxi[1][q] = bx[5*Hh + k]; bxo[1][q] = bx[6*Hh + k]; bxc[1][q] = bx[7*Hh + k];
            bdl[0][q] = bd[k];        bdl[1][q] = bd[Hh + k];
            wtl[0][q] = Wt[k];        wtl[1][q] = Wt[Hh + k];
            btl[0][q] = bt[k];        btl[1][q] = bt[Hh + k];
        }
    }

    // ================= time loop =================
    for (int t = 0; t < Lh; t++) {
        {
            int r = tid >> 4, d = tid & 15;   // 512 threads = 32*16 exactly
            sm->histb[r][d] = history[((size_t)(b0 + r) * Lh + t) * Dh + d];
        }
        if (tid < ROWS)
            sm->msk[tid] = hmask[(size_t)(b0 + tid) * Lh + t];
        __syncthreads();

        if (tid < ROWS) {
            float dd = fmaxf(sm->histb[tid][5], 0.0f);
            sm->dec[tid] = 1.0f / logf(2.718281828459045f + dd);
        }
        // x_t = hist @ Wp + bp  (2 k channels x 4 rows)
        {
            float a0[4], a1[4];
            #pragma unroll
            for (int rr = 0; rr < 4; rr++) { a0[rr] = bpk[0]; a1[rr] = bpk[1]; }
            #pragma unroll
            for (int d = 0; d < Dh; d++) {
                float w0 = sm->wp[d][k0];
                float w1 = sm->wp[d][k1];
                #pragma unroll
                for (int rr = 0; rr < 4; rr++) {
                    float hv = sm->histb[rb + rr][d];
                    a0[rr] += hv * w0;
                    a1[rr] += hv * w1;
                }
            }
            #pragma unroll
            for (int rr = 0; rr < 4; rr++) {
                sm->xin[rb + rr][k0] = a0[rr];
                sm->xin[rb + rr][k1] = a1[rr];
            }
        }
        __syncthreads();

        #pragma unroll
        for (int l = 0; l < 2; l++) {
            const float* inp  = (l == 0) ? &sm->xin[0][0] : &sm->h[0][0][0];
            float*       hcur = &sm->h[l][0][0];

            // packed accumulators: 3 gates x 2 k x 4 rows = 24 ull (48 regs)
            ull zi2[8], zo2[8], zc2[8];
            #pragma unroll
            for (int q = 0; q < 2; q++) {
                #pragma unroll
                for (int rr = 0; rr < 4; rr++) {
                    PACK2(zi2[q*4+rr], bxi[l][q], 0.0f);
                    PACK2(zo2[q*4+rr], bxo[l][q], 0.0f);
                    PACK2(zc2[q*4+rr], bxc[l][q], 0.0f);
                }
            }

            const ulonglong2* __restrict__ pw = &g_wg[l][0][0][0];
            #pragma unroll 2
            for (int p = 0; p < NPAIR; p++) {
                ulonglong2 wa0 = pw[k0];          // (wi,wo) k0
                ulonglong2 wb0 = pw[Hh + k0];     // (wc,ui) k0
                ulonglong2 wc0 = pw[2*Hh + k0];   // (uo,uc) k0
                ulonglong2 wa1 = pw[k1];
                ulonglong2 wb1 = pw[Hh + k1];
                ulonglong2 wc1 = pw[2*Hh + k1];
                const int j = 2 * p;
                #pragma unroll
                for (int rr = 0; rr < 4; rr++) {
                    const int r = rb + rr;
                    ull xu = *reinterpret_cast<const ull*>(inp  + r*Hh + j);
                    ull hu = *reinterpret_cast<const ull*>(hcur + r*Hh + j);
                    FMA2(zi2[rr],   xu, wa0.x);
                    FMA2(zo2[rr],   xu, wa0.y);
                    FMA2(zc2[rr],   xu, wb0.x);
                    FMA2(zi2[rr],   hu, wb0.y);
                    FMA2(zo2[rr],   hu, wc0.x);
                    FMA2(zc2[rr],   hu, wc0.y);
                    FMA2(zi2[4+rr], xu, wa1.x);
                    FMA2(zo2[4+rr], xu, wa1.y);
                    FMA2(zc2[4+rr], xu, wb1.x);
                    FMA2(zi2[4+rr], hu, wb1.y);
                    FMA2(zo2[4+rr], hu, wc1.x);
                    FMA2(zc2[4+rr], hu, wc1.y);
                }
                pw += 3 * Hh;
            }

            float ot[8], htl[8];
            #pragma unroll
            for (int q = 0; q < 2; q++) {
                const int k = q ? k1 : k0;
                #pragma unroll
                for (int rr = 0; rr < 4; rr++) {
                    float2 a = unpack2(zi2[q*4+rr]);
                    float2 b = unpack2(zo2[q*4+rr]);
                    float2 c = unpack2(zc2[q*4+rr]);
                    float it = sig_f(a.x + a.y);
                    ot[q*4+rr]  = sig_f(b.x + b.y);
                    htl[q*4+rr] = tanh_f(c.x + c.y) + it;
                    sm->ht[rb + rr][k] = htl[q*4+rr];
                }
            }
            __syncthreads();

            // h_short = tanh(h_tilde @ Wd + bd)
            const ull* __restrict__ pd = &g_wd[l][0][0];
            ull hs2[8];
            #pragma unroll
            for (int q = 0; q < 2; q++)
                #pragma unroll
                for (int rr = 0; rr < 4; rr++)
                    PACK2(hs2[q*4+rr], bdl[l][q], 0.0f);
            #pragma unroll 4
            for (int p = 0; p < NPAIR; p++) {
                ull wd0 = pd[k0];
                ull wd1 = pd[k1];
                const int j = 2 * p;
                #pragma unroll
                for (int rr = 0; rr < 4; rr++) {
                    ull t2 = *reinterpret_cast<const ull*>(&sm->ht[rb + rr][j]);
                    FMA2(hs2[rr],   t2, wd0);
                    FMA2(hs2[4+rr], t2, wd1);
                }
                pd += Hh;
            }

            #pragma unroll
            for (int q = 0; q < 2; q++) {
                const int k = q ? k1 : k0;
                #pragma unroll
                for (int rr = 0; rr < 4; rr++) {
                    const int r = rb + rr;
                    float2 av   = unpack2(hs2[q*4+rr]);
                    float hs    = tanh_f(av.x + av.y);
                    float dt    = sig_f(sm->dec[r] * wtl[l][q] + btl[l][q]);
                    float hstar = (htl[q*4+rr] - hs) + hs * dt;
                    float cold  = sm->c[l][r][k];
                    float cn    = tanh_f(hstar + ot[q*4+rr] * cold);
                    float hn    = ot[q*4+rr] * tanh_f(cn);
                    float m     = sm->msk[r];
                    float hv    = m * hn + (1.0f - m) * hcur[r*Hh + k];
                    float cv    = m * cn + (1.0f - m) * cold;
                    sm->c[l][r][k] = cv;
                    hcur[r*Hh + k] = hv;
                    if (l == 1 && t == sm->last[r])
                        sm->sv[r][k] = m * hv;
                }
            }
            __syncthreads();
        }
    }

    // ================= forecast head =================
    {
        int r = tid >> 4, d = tid & 15;
        sm->histb[r][d] = history[((size_t)(b0 + r) * Lh + sm->last[r]) * Dh + d];
    }
    __syncthreads();

    const unsigned FULL = 0xffffffffu;
    #pragma unroll
    for (int rr = 0; rr < 2; rr++) {
        const int r = w * 2 + rr;

        float s = 0.0f, s2 = 0.0f;
        for (int i = lane; i < HEAD_IN; i += 32) {
            float v = (i < 16) ? sm->histb[r][i] : sm->sv[r][i - 16];
            s += v; s2 += v * v;
        }
        #pragma unroll
        for (int off = 16; off; off >>= 1) {
            s  += __shfl_xor_sync(FULL, s,  off);
            s2 += __shfl_xor_sync(FULL, s2, off);
        }
        float mean = s / (float)HEAD_IN;
        float var  = s2 / (float)HEAD_IN - mean * mean;
        float rstd = rsqrtf(var + 1e-5f);

        const int j0 = lane * 4;
        float4 acc = *reinterpret_cast<const float4*>(b1 + j0);
        for (int i = 0; i < HEAD_IN; i++) {
            float v  = (i < 16) ? sm->histb[r][i] : sm->sv[r][i - 16];
            float sn = (v - mean) * rstd * ln_g[i] + ln_b[i];
            float4 w4 = *reinterpret_cast<const float4*>(W1 + i * Hh + j0);
            acc.x += sn * w4.x; acc.y += sn * w4.y;
            acc.z += sn * w4.z; acc.w += sn * w4.w;
        }
        float y[4] = { fmaxf(acc.x, 0.0f), fmaxf(acc.y, 0.0f),
                       fmaxf(acc.z, 0.0f), fmaxf(acc.w, 0.0f) };

        const int o0 = lane, o1 = lane + 32;
        float a0 = b2[o0];
        float a1 = (o1 < OUTD) ? b2[o1] : 0.0f;
        #pragma unroll
        for (int q = 0; q < 4; q++) {
            float yq = y[q];
            #pragma unroll 8
            for (int src = 0; src < 32; src++) {
                float v = __shfl_sync(FULL, yq, src);
                int   j = src * 4 + q;
                a0 += v * W2[j * OUTD + o0];
                if (o1 < OUTD) a1 += v * W2[j * OUTD + o1];
            }
        }
        size_t ob = (size_t)(b0 + r) * OUTD;
        out[ob + o0] = fixv(a0);
        if (o1 < OUTD) out[ob + o1] = fixv(a1);
    }
}

extern "C" void kernel_launch(void* const* d_in, const int* in_sizes, int n_in,
                              void* d_out, int out_size)
{
    const float* history = (const float*)d_in[0];
    const float* hmask   = (const float*)d_in[1];
    const float* Wp      = (const float*)d_in[2];
    const float* bp      = (const float*)d_in[3];
    const float* Wx      = (const float*)d_in[4];
    const float* bx      = (const float*)d_in[5];
    const float* Uh      = (const float*)d_in[6];
    const float* Wd      = (const float*)d_in[7];
    const float* bd      = (const float*)d_in[8];
    const float* Wt      = (const float*)d_in[9];
    const float* bt      = (const float*)d_in[10];
    const float* ln_g    = (const float*)d_in[11];
    const float* ln_b    = (const float*)d_in[12];
    const float* W1      = (const float*)d_in[13];
    const float* b1      = (const float*)d_in[14];
    const float* W2      = (const float*)d_in[15];
    const float* b2      = (const float*)d_in[16];

    pack_kernel<<<(2 * NPAIR * Hh + 255) / 256, 256>>>(Wx, Uh, Wd);

    cudaFuncSetAttribute(tlstm_kernel,
                         cudaFuncAttributeMaxDynamicSharedMemorySize,
                         (int)sizeof(SM));
    tlstm_kernel<<<CTAS, THREADS, sizeof(SM)>>>(
        history, hmask, Wp, bp, bx, bd, Wt, bt,
        ln_g, ln_b, W1, b1, W2, b2, (float*)d_out);
}

// round 10
// speedup vs baseline: 2.8951x; 2.8901x over previous
#include <cuda_runtime.h>
#include <cuda_bf16.h>
#include <math.h>
#include <stdint.h>

#define Lh    64
#define Dh    16
#define Hh    128
#define ROWS  32
#define THREADS 256
#define CTAS  128
#define HEAD_IN 144
#define OUTD  60

typedef unsigned long long ull;

// ---- SMEM layout (bytes). A images: 32 rows x 264 bf16 (stride 528B). HT: stride 272B.
#define OFF_A0H   0
#define OFF_A0L   16896
#define OFF_A1H   33792
#define OFF_A1L   50688
#define OFF_HTH   67584
#define OFF_HTL   76288
#define OFF_SV    84992
#define OFF_WP    101376
#define OFF_HISTB 109568
#define OFF_MSK   111616
#define OFF_DEC   111744
#define OFF_LAST  111872
#define OFF_BX    112000
#define OFF_BD    115072
#define OFF_WT    116096
#define OFF_BT    117120
#define OFF_BP    118144
#define SMEM_TOTAL 118656
#define F(off) ((off) >> 2)
#define ASTR 528
#define HSTR 272

// weight blobs in per-lane fragment order
// gates: [l][img][kt(16)][ntile(48)][lane(32)] 8B ; ntile = gate*16 + (ktile_out)
__device__ ull g_gb[2*2*16*48*32];
// Wd: [l][img][kt(8)][ntile(16)][lane(32)] 8B
__device__ ull g_wb[2*2*8*16*32];

__global__ void pack_kernel(const float* __restrict__ Wx,
                            const float* __restrict__ Uh,
                            const float* __restrict__ Wd)
{
    int idx = blockIdx.x * blockDim.x + threadIdx.x;
    if (idx < 98304) {
        int lane = idx & 31; int q = idx >> 5;
        int nt = q % 48; q /= 48;
        int kt = q & 15; q >>= 4;
        int img = q & 1; int l = q >> 1;
        int gate = nt / 16;
        int n  = (nt % 16) * 8 + (lane >> 2);
        int kb = kt * 16 + (lane & 3) * 2;
        ull outv = 0;
        #pragma unroll
        for (int e = 0; e < 4; e++) {
            int kk = kb + (e & 1) + (e >> 1) * 8;   // kb, kb+1, kb+8, kb+9
            float v = (kk < 128)
                ? Wx[((size_t)(l*4 + gate + 1) * 128 + kk) * 128 + n]
                : Uh[((size_t)(l*4 + gate + 1) * 128 + (kk - 128)) * 128 + n];
            __nv_bfloat16 hi = __float2bfloat16(v);
            __nv_bfloat16 res = img ? __float2bfloat16(v - __bfloat162float(hi)) : hi;
            outv |= (ull)(*(unsigned short*)&res) << (16 * e);
        }
        g_gb[idx] = outv;
    } else if (idx < 98304 + 16384) {
        int i2 = idx - 98304;
        int lane = i2 & 31; int q = i2 >> 5;
        int nt = q & 15; q >>= 4;
        int kt = q & 7;  q >>= 3;
        int img = q & 1; int l = q >> 1;
        int n  = nt * 8 + (lane >> 2);
        int kb = kt * 16 + (lane & 3) * 2;
        ull outv = 0;
        #pragma unroll
        for (int e = 0; e < 4; e++) {
            int kk = kb + (e & 1) + (e >> 1) * 8;
            float v = Wd[((size_t)l * 128 + kk) * 128 + n];
            __nv_bfloat16 hi = __float2bfloat16(v);
            __nv_bfloat16 res = img ? __float2bfloat16(v - __bfloat162float(hi)) : hi;
            outv |= (ull)(*(unsigned short*)&res) << (16 * e);
        }
        g_wb[i2] = outv;
    }
}

__device__ __forceinline__ uint32_t smem_u32(const void* p) {
    uint32_t a;
    asm("{ .reg .u64 t; cvta.to.shared.u64 t, %1; cvt.u32.u64 %0, t; }" : "=r"(a) : "l"(p));
    return a;
}
__device__ __forceinline__ void ldm4(uint32_t* r, uint32_t addr) {
    asm volatile("ldmatrix.sync.aligned.m8n8.x4.shared.b16 {%0,%1,%2,%3}, [%4];"
        : "=r"(r[0]), "=r"(r[1]), "=r"(r[2]), "=r"(r[3]) : "r"(addr));
}
__device__ __forceinline__ void mma16816(float* c, const uint32_t* a, uint32_t b0, uint32_t b1) {
    asm volatile("mma.sync.aligned.m16n8k16.row.col.f32.bf16.bf16.f32 "
        "{%0,%1,%2,%3}, {%4,%5,%6,%7}, {%8,%9}, {%0,%1,%2,%3};"
        : "+f"(c[0]), "+f"(c[1]), "+f"(c[2]), "+f"(c[3])
        : "r"(a[0]), "r"(a[1]), "r"(a[2]), "r"(a[3]), "r"(b0), "r"(b1));
}
__device__ __forceinline__ void split2(float x, float y, uint32_t& hi, uint32_t& lo) {
    __nv_bfloat16 hx = __float2bfloat16(x), hy = __float2bfloat16(y);
    __nv_bfloat16 lx = __float2bfloat16(x - __bfloat162float(hx));
    __nv_bfloat16 ly = __float2bfloat16(y - __bfloat162float(hy));
    hi = (uint32_t)(*(unsigned short*)&hx) | ((uint32_t)(*(unsigned short*)&hy) << 16);
    lo = (uint32_t)(*(unsigned short*)&lx) | ((uint32_t)(*(unsigned short*)&ly) << 16);
}
__device__ __forceinline__ float tanh_f(float x) {
    float e = __expf(2.0f * x);
    return 1.0f - __fdividef(2.0f, e + 1.0f);
}
__device__ __forceinline__ float sig_f(float x) {
    return __fdividef(1.0f, 1.0f + __expf(-x));
}
__device__ __forceinline__ float fixv(float x) {
    if (!(x == x)) return 0.0f;
    if (x > 1e38f) return 1e4f;
    if (x < -1e38f) return -1e4f;
    return x;
}

__global__ void __launch_bounds__(THREADS, 1)
tlstm_mma_kernel(const float* __restrict__ history, const float* __restrict__ hmask,
                 const float* __restrict__ Wp,  const float* __restrict__ bp,
                 const float* __restrict__ bx,  const float* __restrict__ bd,
                 const float* __restrict__ Wt,  const float* __restrict__ bt,
                 const float* __restrict__ ln_g, const float* __restrict__ ln_b,
                 const float* __restrict__ W1,  const float* __restrict__ b1,
                 const float* __restrict__ W2,  const float* __restrict__ b2,
                 float* __restrict__ out)
{
    extern __shared__ char sm[];
    float* smf = (float*)sm;
    int*   lastArr = (int*)(sm + OFF_LAST);
    const uint32_t smb = smem_u32(sm);

    const int tid  = threadIdx.x;
    const int b0   = blockIdx.x * ROWS;
    const int w    = tid >> 5;
    const int lane = tid & 31;
    const int g4   = lane >> 2;
    const int c4   = lane & 3;

    // ldmatrix per-lane byte offsets within an image
    const int lm_row = (lane & 7) + ((lane >> 3) & 1) * 8;
    const int lm_k8  = ((lane >> 4) & 1) * 8;
    const int lmA0 = lm_row * ASTR + lm_k8 * 2;
    const int lmA1 = (lm_row + 16) * ASTR + lm_k8 * 2;
    const int lmH0 = lm_row * HSTR + lm_k8 * 2;
    const int lmH1 = (lm_row + 16) * HSTR + lm_k8 * 2;

    // ---- init ----
    for (int i = tid; i < 67584 / 4; i += THREADS)   // zero A0H..A1L
        ((uint32_t*)sm)[i] = 0;
    for (int i = tid; i < Dh * Hh; i += THREADS)
        smf[F(OFF_WP) + i] = Wp[i];
    for (int i = tid; i < 768; i += THREADS) {       // bx: [l][gate(i,o,c)][k]
        int l = i / 384, gi = (i % 384) / 128, k = i & 127;
        smf[F(OFF_BX) + i] = bx[(l*4 + gi + 1)*128 + k];
    }
    if (tid < 256) smf[F(OFF_BD) + tid] = bd[tid];
    if (tid < 256) smf[F(OFF_WT) + tid] = Wt[tid];
    if (tid < 256) smf[F(OFF_BT) + tid] = bt[tid];
    if (tid < 128) smf[F(OFF_BP) + tid] = bp[tid];
    if (tid < ROWS) {
        const float* mp = hmask + (size_t)(b0 + tid) * Lh;
        float s = 0.0f;
        for (int t = 0; t < Lh; t++) s += mp[t];
        s = fminf(fmaxf(s, 1.0f), (float)Lh);
        lastArr[tid] = (int)s - 1;
    }
    __syncthreads();

    // per-lane register state: [layer][mt*8 + nt*4 + r]
    float cS[2][16], hS[2][16];
    #pragma unroll
    for (int l = 0; l < 2; l++)
        #pragma unroll
        for (int i = 0; i < 16; i++) { cS[l][i] = 0.0f; hS[l][i] = 0.0f; }

    // ================= time loop =================
    for (int t = 0; t < Lh; t++) {
        for (int i = tid; i < ROWS * Dh; i += THREADS) {
            int r = i >> 4, d = i & 15;
            smf[F(OFF_HISTB) + r*16 + d] = history[((size_t)(b0 + r) * Lh + t) * Dh + d];
        }
        if (tid < ROWS)
            smf[F(OFF_MSK) + tid] = hmask[(size_t)(b0 + tid) * Lh + t];
        __syncthreads();

        if (tid < ROWS) {
            float dd = fmaxf(smf[F(OFF_HISTB) + tid*16 + 5], 0.0f);
            smf[F(OFF_DEC) + tid] = 1.0f / logf(2.718281828459045f + dd);
        }
        // x = hist @ Wp + bp ; write bf16 hi/lo into A0 x-half
        {
            int row = tid >> 3;
            int kb  = (tid & 7) * 16;
            float acc[16];
            #pragma unroll
            for (int ii = 0; ii < 16; ii++) acc[ii] = smf[F(OFF_BP) + kb + ii];
            #pragma unroll
            for (int d = 0; d < Dh; d++) {
                float hv = smf[F(OFF_HISTB) + row*16 + d];
                #pragma unroll
                for (int ii = 0; ii < 16; ii++)
                    acc[ii] += hv * smf[F(OFF_WP) + d*128 + kb + ii];
            }
            #pragma unroll
            for (int ii = 0; ii < 8; ii++) {
                uint32_t hi, lo;
                split2(acc[2*ii], acc[2*ii+1], hi, lo);
                *(uint32_t*)(sm + OFF_A0H + row*ASTR + (kb + 2*ii)*2) = hi;
                *(uint32_t*)(sm + OFF_A0L + row*ASTR + (kb + 2*ii)*2) = lo;
            }
        }
        __syncthreads();

        #pragma unroll
        for (int l = 0; l < 2; l++) {
            const uint32_t aHb = smb + (l ? OFF_A1H : OFF_A0H);
            const uint32_t aLb = smb + (l ? OFF_A1L : OFF_A0L);

            // ---- gate GEMM: Z[32 x (3x128)] over K=256 ----
            float zC[3][16];
            #pragma unroll
            for (int gi = 0; gi < 3; gi++)
                #pragma unroll
                for (int i = 0; i < 16; i++) zC[gi][i] = 0.0f;

            const ull* gbL = g_gb + (size_t)l * 49152;
            #pragma unroll 2
            for (int kt = 0; kt < 16; kt++) {
                uint32_t ah0[4], ah1[4], al0[4], al1[4];
                ldm4(ah0, aHb + lmA0 + kt*32);
                ldm4(ah1, aHb + lmA1 + kt*32);
                ldm4(al0, aLb + lmA0 + kt*32);
                ldm4(al1, aLb + lmA1 + kt*32);
                #pragma unroll
                for (int gi = 0; gi < 3; gi++) {
                    #pragma unroll
                    for (int nt = 0; nt < 2; nt++) {
                        int ntile = gi*16 + w*2 + nt;
                        const ull* pb = gbL + ((size_t)kt*48 + ntile)*32 + lane;
                        ull vh = pb[0], vl = pb[24576];
                        uint32_t bh0 = (uint32_t)vh, bh1 = (uint32_t)(vh >> 32);
                        uint32_t bl0 = (uint32_t)vl, bl1 = (uint32_t)(vl >> 32);
                        float* c0 = &zC[gi][nt*4];
                        float* c1 = &zC[gi][8 + nt*4];
                        mma16816(c0, ah0, bh0, bh1);
                        mma16816(c1, ah1, bh0, bh1);
                        mma16816(c0, ah0, bl0, bl1);
                        mma16816(c1, ah1, bl0, bl1);
                        mma16816(c0, al0, bh0, bh1);
                        mma16816(c1, al1, bh0, bh1);
                    }
                }
            }

            // ---- epilogue 1: gates -> h_tilde, write HT ----
            float ot[16], htl[16];
            #pragma unroll
            for (int mt = 0; mt < 2; mt++) {
                #pragma unroll
                for (int nt = 0; nt < 2; nt++) {
                    int i0 = mt*8 + nt*4;
                    int kbase = (w << 4) + nt*8 + (c4 << 1);
                    float hts[4];
                    #pragma unroll
                    for (int rr = 0; rr < 4; rr++) {
                        int idx = i0 + rr;
                        int k   = kbase + (rr & 1);
                        float zi = zC[0][idx] + smf[F(OFF_BX) + (l*3 + 0)*128 + k];
                        float zo = zC[1][idx] + smf[F(OFF_BX) + (l*3 + 1)*128 + k];
                        float zc = zC[2][idx] + smf[F(OFF_BX) + (l*3 + 2)*128 + k];
                        float it = sig_f(zi);
                        ot[idx]  = sig_f(zo);
                        htl[idx] = tanh_f(zc) + it;
                        hts[rr]  = htl[idx];
                    }
                    uint32_t h01, l01, h23, l23;
                    split2(hts[0], hts[1], h01, l01);
                    split2(hts[2], hts[3], h23, l23);
                    int row0 = g4 + mt*16, row1 = row0 + 8;
                    *(uint32_t*)(sm + OFF_HTH + row0*HSTR + kbase*2) = h01;
                    *(uint32_t*)(sm + OFF_HTL + row0*HSTR + kbase*2) = l01;
                    *(uint32_t*)(sm + OFF_HTH + row1*HSTR + kbase*2) = h23;
                    *(uint32_t*)(sm + OFF_HTL + row1*HSTR + kbase*2) = l23;
                }
            }
            __syncthreads();

            // ---- Wd GEMM: Hs[32x128] over K=128 ----
            float zD[16];
            #pragma unroll
            for (int i = 0; i < 16; i++) zD[i] = 0.0f;
            const ull* wbL = g_wb + (size_t)l * 8192;
            #pragma unroll 2
            for (int kt = 0; kt < 8; kt++) {
                uint32_t hh0[4], hh1[4], hl0[4], hl1[4];
                ldm4(hh0, smb + OFF_HTH + lmH0 + kt*32);
                ldm4(hh1, smb + OFF_HTH + lmH1 + kt*32);
                ldm4(hl0, smb + OFF_HTL + lmH0 + kt*32);
                ldm4(hl1, smb + OFF_HTL + lmH1 + kt*32);
                #pragma unroll
                for (int nt = 0; nt < 2; nt++) {
                    int ntile = w*2 + nt;
                    const ull* pb = wbL + ((size_t)kt*16 + ntile)*32 + lane;
                    ull vh = pb[0], vl = pb[4096];
                    uint32_t bh0 = (uint32_t)vh, bh1 = (uint32_t)(vh >> 32);
                    uint32_t bl0 = (uint32_t)vl, bl1 = (uint32_t)(vl >> 32);
                    mma16816(&zD[nt*4],     hh0, bh0, bh1);
                    mma16816(&zD[8 + nt*4], hh1, bh0, bh1);
                    mma16816(&zD[nt*4],     hh0, bl0, bl1);
                    mma16816(&zD[8 + nt*4], hh1, bl0, bl1);
                    mma16816(&zD[nt*4],     hl0, bh0, bh1);
                    mma16816(&zD[8 + nt*4], hl1, bh0, bh1);
                }
            }

            // ---- epilogue 2: recurrence, state update, write h operand ----
            float dec4[4], msk4[4];
            int lst4[4];
            #pragma unroll
            for (int q = 0; q < 4; q++) {
                int row = g4 + q*8;
                dec4[q] = smf[F(OFF_DEC) + row];
                msk4[q] = smf[F(OFF_MSK) + row];
                lst4[q] = lastArr[row];
            }
            #pragma unroll
            for (int mt = 0; mt < 2; mt++) {
                #pragma unroll
                for (int nt = 0; nt < 2; nt++) {
                    int i0 = mt*8 + nt*4;
                    int kbase = (w << 4) + nt*8 + (c4 << 1);
                    float hvv[4];
                    #pragma unroll
                    for (int rr = 0; rr < 4; rr++) {
                        int idx = i0 + rr;
                        int q   = mt*2 + (rr >> 1);
                        int k   = kbase + (rr & 1);
                        float hs    = tanh_f(zD[idx] + smf[F(OFF_BD) + l*128 + k]);
                        float dt    = sig_f(dec4[q] * smf[F(OFF_WT) + l*128 + k]
                                            + smf[F(OFF_BT) + l*128 + k]);
                        float hstar = (htl[idx] - hs) + hs * dt;
                        float cold  = cS[l][idx];
                        float cn    = tanh_f(hstar + ot[idx] * cold);
                        float hn    = ot[idx] * tanh_f(cn);
                        float m     = msk4[q];
                        float hv    = m * hn + (1.0f - m) * hS[l][idx];
                        float cv    = m * cn + (1.0f - m) * cold;
                        cS[l][idx] = cv;
                        hS[l][idx] = hv;
                        hvv[rr] = hv;
                        if (l == 1 && t == lst4[q])
                            smf[F(OFF_SV) + (g4 + mt*16 + ((rr >> 1) << 3))*128 + k] = m * hv;
                    }
                    uint32_t h01, l01, h23, l23;
                    split2(hvv[0], hvv[1], h01, l01);
                    split2(hvv[2], hvv[3], h23, l23);
                    int row0 = g4 + mt*16, row1 = row0 + 8;
                    if (l == 0) {
                        *(uint32_t*)(sm + OFF_A1H + row0*ASTR + kbase*2) = h01;
                        *(uint32_t*)(sm + OFF_A1L + row0*ASTR + kbase*2) = l01;
                        *(uint32_t*)(sm + OFF_A1H + row1*ASTR + kbase*2) = h23;
                        *(uint32_t*)(sm + OFF_A1L + row1*ASTR + kbase*2) = l23;
                        *(uint32_t*)(sm + OFF_A0H + row0*ASTR + 256 + kbase*2) = h01;
                        *(uint32_t*)(sm + OFF_A0L + row0*ASTR + 256 + kbase*2) = l01;
                        *(uint32_t*)(sm + OFF_A0H + row1*ASTR + 256 + kbase*2) = h23;
                        *(uint32_t*)(sm + OFF_A0L + row1*ASTR + 256 + kbase*2) = l23;
                    } else {
                        *(uint32_t*)(sm + OFF_A1H + row0*ASTR + 256 + kbase*2) = h01;
                        *(uint32_t*)(sm + OFF_A1L + row0*ASTR + 256 + kbase*2) = l01;
                        *(uint32_t*)(sm + OFF_A1H + row1*ASTR + 256 + kbase*2) = h23;
                        *(uint32_t*)(sm + OFF_A1L + row1*ASTR + 256 + kbase*2) = l23;
                    }
                }
            }
            __syncthreads();
        }
    }

    // ================= forecast head =================
    for (int i = tid; i < ROWS * Dh; i += THREADS) {
        int r = i >> 4, d = i & 15;
        smf[F(OFF_HISTB) + r*16 + d] =
            history[((size_t)(b0 + r) * Lh + lastArr[r]) * Dh + d];
    }
    __syncthreads();

    const unsigned FULL = 0xffffffffu;
    #pragma unroll
    for (int rr = 0; rr < 4; rr++) {
        const int r = w * 4 + rr;

        float s = 0.0f, s2 = 0.0f;
        for (int i = lane; i < HEAD_IN; i += 32) {
            float v = (i < 16) ? smf[F(OFF_HISTB) + r*16 + i]
                               : smf[F(OFF_SV) + r*128 + (i - 16)];
            s += v; s2 += v * v;
        }
        #pragma unroll
        for (int off = 16; off; off >>= 1) {
            s  += __shfl_xor_sync(FULL, s,  off);
            s2 += __shfl_xor_sync(FULL, s2, off);
        }
        float mean = s / (float)HEAD_IN;
        float var  = s2 / (float)HEAD_IN - mean * mean;
        float rstd = rsqrtf(var + 1e-5f);

        const int j0 = lane * 4;
        float4 acc = *reinterpret_cast<const float4*>(b1 + j0);
        for (int i = 0; i < HEAD_IN; i++) {
            float v  = (i < 16) ? smf[F(OFF_HISTB) + r*16 + i]
                                : smf[F(OFF_SV) + r*128 + (i - 16)];
            float sn = (v - mean) * rstd * ln_g[i] + ln_b[i];
            float4 w4 = *reinterpret_cast<const float4*>(W1 + i * Hh + j0);
            acc.x += sn * w4.x; acc.y += sn * w4.y;
            acc.z += sn * w4.z; acc.w += sn * w4.w;
        }
        float y[4] = { fmaxf(acc.x, 0.0f), fmaxf(acc.y, 0.0f),
                       fmaxf(acc.z, 0.0f), fmaxf(acc.w, 0.0f) };

        const int o0 = lane, o1 = lane + 32;
        float a0 = b2[o0];
        float a1 = (o1 < OUTD) ? b2[o1] : 0.0f;
        #pragma unroll
        for (int q = 0; q < 4; q++) {
            float yq = y[q];
            #pragma unroll 8
            for (int src = 0; src < 32; src++) {
                float v = __shfl_sync(FULL, yq, src);
                int   j = src * 4 + q;
                a0 += v * W2[j * OUTD + o0];
                if (o1 < OUTD) a1 += v * W2[j * OUTD + o1];
            }
        }
        size_t ob = (size_t)(b0 + r) * OUTD;
        out[ob + o0] = fixv(a0);
        if (o1 < OUTD) out[ob + o1] = fixv(a1);
    }
}

extern "C" void kernel_launch(void* const* d_in, const int* in_sizes, int n_in,
                              void* d_out, int out_size)
{
    const float* history = (const float*)d_in[0];
    const float* hmask   = (const float*)d_in[1];
    const float* Wp      = (const float*)d_in[2];
    const float* bp      = (const float*)d_in[3];
    const float* Wx      = (const float*)d_in[4];
    const float* bx      = (const float*)d_in[5];
    const float* Uh      = (const float*)d_in[6];
    const float* Wd      = (const float*)d_in[7];
    const float* bd      = (const float*)d_in[8];
    const float* Wt      = (const float*)d_in[9];
    const float* bt      = (const float*)d_in[10];
    const float* ln_g    = (const float*)d_in[11];
    const float* ln_b    = (const float*)d_in[12];
    const float* W1      = (const float*)d_in[13];
    const float* b1      = (const float*)d_in[14];
    const float* W2      = (const float*)d_in[15];
    const float* b2      = (const float*)d_in[16];

    pack_kernel<<<448, 256>>>(Wx, Uh, Wd);

    cudaFuncSetAttribute(tlstm_mma_kernel,
                         cudaFuncAttributeMaxDynamicSharedMemorySize, SMEM_TOTAL);
    tlstm_mma_kernel<<<CTAS, THREADS, SMEM_TOTAL>>>(
        history, hmask, Wp, bp, bx, bd, Wt, bt,
        ln_g, ln_b, W1, b1, W2, b2, (float*)d_out);
}

// round 11
// speedup vs baseline: 3.2347x; 1.1173x over previous
#include <cuda_runtime.h>
#include <cuda_bf16.h>
#include <math.h>
#include <stdint.h>

#define Lh    64
#define Dh    16
#define Hh    128
#define ROWS  32
#define THREADS 512
#define CTAS  128
#define HEAD_IN 144
#define OUTD  60

typedef unsigned long long ull;

// ---- SMEM layout (bytes). A images: 32 rows x 264 bf16 (stride 528B). HT: stride 272B.
#define OFF_A0H   0
#define OFF_A0L   16896
#define OFF_A1H   33792
#define OFF_A1L   50688
#define OFF_HTH   67584
#define OFF_HTL   76288
#define OFF_SV    84992
#define OFF_WP    101376
#define OFF_HISTB 109568
#define OFF_MSK   111616
#define OFF_DEC   111744
#define OFF_LAST  111872
#define OFF_BX    112000
#define OFF_BD    115072
#define OFF_WT    116096
#define OFF_BT    117120
#define OFF_BP    118144
#define SMEM_TOTAL 118656
#define F(off) ((off) >> 2)
#define ASTR 528
#define HSTR 272

// weight blobs in per-lane fragment order
// gates: [l][img][kt(16)][ntile(48)][lane(32)] 8B ; ntile = gate*16 + wk*2 + nt
__device__ ull g_gb[2*2*16*48*32];
// Wd: [l][img][kt(8)][ntile(16)][lane(32)] 8B
__device__ ull g_wb[2*2*8*16*32];

__global__ void pack_kernel(const float* __restrict__ Wx,
                            const float* __restrict__ Uh,
                            const float* __restrict__ Wd)
{
    int idx = blockIdx.x * blockDim.x + threadIdx.x;
    if (idx < 98304) {
        int lane = idx & 31; int q = idx >> 5;
        int nt = q % 48; q /= 48;
        int kt = q & 15; q >>= 4;
        int img = q & 1; int l = q >> 1;
        int gate = nt / 16;
        int n  = (nt % 16) * 8 + (lane >> 2);
        int kb = kt * 16 + (lane & 3) * 2;
        ull outv = 0;
        #pragma unroll
        for (int e = 0; e < 4; e++) {
            int kk = kb + (e & 1) + (e >> 1) * 8;   // kb, kb+1, kb+8, kb+9
            float v = (kk < 128)
                ? Wx[((size_t)(l*4 + gate + 1) * 128 + kk) * 128 + n]
                : Uh[((size_t)(l*4 + gate + 1) * 128 + (kk - 128)) * 128 + n];
            __nv_bfloat16 hi = __float2bfloat16(v);
            __nv_bfloat16 res = img ? __float2bfloat16(v - __bfloat162float(hi)) : hi;
            outv |= (ull)(*(unsigned short*)&res) << (16 * e);
        }
        g_gb[idx] = outv;
    } else if (idx < 98304 + 16384) {
        int i2 = idx - 98304;
        int lane = i2 & 31; int q = i2 >> 5;
        int nt = q & 15; q >>= 4;
        int kt = q & 7;  q >>= 3;
        int img = q & 1; int l = q >> 1;
        int n  = nt * 8 + (lane >> 2);
        int kb = kt * 16 + (lane & 3) * 2;
        ull outv = 0;
        #pragma unroll
        for (int e = 0; e < 4; e++) {
            int kk = kb + (e & 1) + (e >> 1) * 8;
            float v = Wd[((size_t)l * 128 + kk) * 128 + n];
            __nv_bfloat16 hi = __float2bfloat16(v);
            __nv_bfloat16 res = img ? __float2bfloat16(v - __bfloat162float(hi)) : hi;
            outv |= (ull)(*(unsigned short*)&res) << (16 * e);
        }
        g_wb[i2] = outv;
    }
}

__device__ __forceinline__ uint32_t smem_u32(const void* p) {
    uint32_t a;
    asm("{ .reg .u64 t; cvta.to.shared.u64 t, %1; cvt.u32.u64 %0, t; }" : "=r"(a) : "l"(p));
    return a;
}
__device__ __forceinline__ void ldm4(uint32_t* r, uint32_t addr) {
    asm volatile("ldmatrix.sync.aligned.m8n8.x4.shared.b16 {%0,%1,%2,%3}, [%4];"
        : "=r"(r[0]), "=r"(r[1]), "=r"(r[2]), "=r"(r[3]) : "r"(addr));
}
__device__ __forceinline__ void mma16816(float* c, const uint32_t* a, uint32_t b0, uint32_t b1) {
    asm volatile("mma.sync.aligned.m16n8k16.row.col.f32.bf16.bf16.f32 "
        "{%0,%1,%2,%3}, {%4,%5,%6,%7}, {%8,%9}, {%0,%1,%2,%3};"
        : "+f"(c[0]), "+f"(c[1]), "+f"(c[2]), "+f"(c[3])
        : "r"(a[0]), "r"(a[1]), "r"(a[2]), "r"(a[3]), "r"(b0), "r"(b1));
}
__device__ __forceinline__ void split2(float x, float y, uint32_t& hi, uint32_t& lo) {
    __nv_bfloat16 hx = __float2bfloat16(x), hy = __float2bfloat16(y);
    __nv_bfloat16 lx = __float2bfloat16(x - __bfloat162float(hx));
    __nv_bfloat16 ly = __float2bfloat16(y - __bfloat162float(hy));
    hi = (uint32_t)(*(unsigned short*)&hx) | ((uint32_t)(*(unsigned short*)&hy) << 16);
    lo = (uint32_t)(*(unsigned short*)&lx) | ((uint32_t)(*(unsigned short*)&ly) << 16);
}
__device__ __forceinline__ float tanh_f(float x) {
    float e = __expf(2.0f * x);
    return 1.0f - __fdividef(2.0f, e + 1.0f);
}
__device__ __forceinline__ float sig_f(float x) {
    return __fdividef(1.0f, 1.0f + __expf(-x));
}
__device__ __forceinline__ float fixv(float x) {
    if (!(x == x)) return 0.0f;
    if (x > 1e38f) return 1e4f;
    if (x < -1e38f) return -1e4f;
    return x;
}

__global__ void __launch_bounds__(THREADS, 1)
tlstm_mma_kernel(const float* __restrict__ history, const float* __restrict__ hmask,
                 const float* __restrict__ Wp,  const float* __restrict__ bp,
                 const float* __restrict__ bx,  const float* __restrict__ bd,
                 const float* __restrict__ Wt,  const float* __restrict__ bt,
                 const float* __restrict__ ln_g, const float* __restrict__ ln_b,
                 const float* __restrict__ W1,  const float* __restrict__ b1,
                 const float* __restrict__ W2,  const float* __restrict__ b2,
                 float* __restrict__ out)
{
    extern __shared__ char sm[];
    float* smf = (float*)sm;
    int*   lastArr = (int*)(sm + OFF_LAST);
    const uint32_t smb = smem_u32(sm);

    const int tid  = threadIdx.x;
    const int b0   = blockIdx.x * ROWS;
    const int w    = tid >> 5;
    const int lane = tid & 31;
    const int wk   = w & 7;          // 8 k-warps: n-range [16wk, 16wk+16)
    const int wr   = w >> 3;         // 2 row groups: rows [16wr, 16wr+16)
    const int g4   = lane >> 2;
    const int c4   = lane & 3;

    // ldmatrix per-lane byte offsets within an image (this warp's m-tile)
    const int lm_row = (lane & 7) + ((lane >> 3) & 1) * 8 + wr * 16;
    const int lm_k8  = ((lane >> 4) & 1) * 8;
    const int lmA = lm_row * ASTR + lm_k8 * 2;
    const int lmH = lm_row * HSTR + lm_k8 * 2;

    // ---- init ----
    for (int i = tid; i < 67584 / 4; i += THREADS)   // zero A0H..A1L
        ((uint32_t*)sm)[i] = 0;
    for (int i = tid; i < Dh * Hh; i += THREADS)
        smf[F(OFF_WP) + i] = Wp[i];
    for (int i = tid; i < 768; i += THREADS) {       // bx: [l][gate(i,o,c)][k]
        int l = i / 384, gi = (i % 384) / 128, k = i & 127;
        smf[F(OFF_BX) + i] = bx[(l*4 + gi + 1)*128 + k];
    }
    if (tid < 256) smf[F(OFF_BD) + tid] = bd[tid];
    if (tid < 256) smf[F(OFF_WT) + tid] = Wt[tid];
    if (tid < 256) smf[F(OFF_BT) + tid] = bt[tid];
    if (tid < 128) smf[F(OFF_BP) + tid] = bp[tid];
    if (tid < ROWS) {
        const float* mp = hmask + (size_t)(b0 + tid) * Lh;
        float s = 0.0f;
        for (int t = 0; t < Lh; t++) s += mp[t];
        s = fminf(fmaxf(s, 1.0f), (float)Lh);
        lastArr[tid] = (int)s - 1;
    }
    __syncthreads();

    // per-lane register state: [layer][nt*4 + r]
    float cS[2][8], hS[2][8];
    #pragma unroll
    for (int l = 0; l < 2; l++)
        #pragma unroll
        for (int i = 0; i < 8; i++) { cS[l][i] = 0.0f; hS[l][i] = 0.0f; }

    // ================= time loop =================
    for (int t = 0; t < Lh; t++) {
        {
            int r = tid >> 4, d = tid & 15;    // 512 = 32 x 16
            smf[F(OFF_HISTB) + r*16 + d] = history[((size_t)(b0 + r) * Lh + t) * Dh + d];
        }
        if (tid < ROWS)
            smf[F(OFF_MSK) + tid] = hmask[(size_t)(b0 + tid) * Lh + t];
        __syncthreads();

        if (tid < ROWS) {
            float dd = fmaxf(smf[F(OFF_HISTB) + tid*16 + 5], 0.0f);
            smf[F(OFF_DEC) + tid] = 1.0f / logf(2.718281828459045f + dd);
        }
        // x = hist @ Wp + bp ; 32 rows x 16 threads, 8 channels per thread
        {
            int row = tid >> 4;
            int kb  = (tid & 15) * 8;
            float acc[8];
            #pragma unroll
            for (int ii = 0; ii < 8; ii++) acc[ii] = smf[F(OFF_BP) + kb + ii];
            #pragma unroll
            for (int d = 0; d < Dh; d++) {
                float hv = smf[F(OFF_HISTB) + row*16 + d];
                #pragma unroll
                for (int ii = 0; ii < 8; ii++)
                    acc[ii] += hv * smf[F(OFF_WP) + d*128 + kb + ii];
            }
            #pragma unroll
            for (int ii = 0; ii < 4; ii++) {
                uint32_t hi, lo;
                split2(acc[2*ii], acc[2*ii+1], hi, lo);
                *(uint32_t*)(sm + OFF_A0H + row*ASTR + (kb + 2*ii)*2) = hi;
                *(uint32_t*)(sm + OFF_A0L + row*ASTR + (kb + 2*ii)*2) = lo;
            }
        }
        __syncthreads();

        #pragma unroll
        for (int l = 0; l < 2; l++) {
            const uint32_t aHb = smb + (l ? OFF_A1H : OFF_A0H);
            const uint32_t aLb = smb + (l ? OFF_A1L : OFF_A0L);

            // ---- gate GEMM: this warp's m-tile, n-range [16wk,16wk+16), K=256 ----
            float zC[3][8];
            #pragma unroll
            for (int gi = 0; gi < 3; gi++)
                #pragma unroll
                for (int i = 0; i < 8; i++) zC[gi][i] = 0.0f;

            const ull* gbL = g_gb + (size_t)l * 49152;
            #pragma unroll 2
            for (int kt = 0; kt < 16; kt++) {
                uint32_t ah[4], al[4];
                ldm4(ah, aHb + lmA + kt*32);
                ldm4(al, aLb + lmA + kt*32);
                #pragma unroll
                for (int gi = 0; gi < 3; gi++) {
                    #pragma unroll
                    for (int nt = 0; nt < 2; nt++) {
                        int ntile = gi*16 + wk*2 + nt;
                        const ull* pb = gbL + ((size_t)kt*48 + ntile)*32 + lane;
                        ull vh = pb[0], vl = pb[24576];
                        uint32_t bh0 = (uint32_t)vh, bh1 = (uint32_t)(vh >> 32);
                        uint32_t bl0 = (uint32_t)vl, bl1 = (uint32_t)(vl >> 32);
                        float* c0 = &zC[gi][nt*4];
                        mma16816(c0, ah, bh0, bh1);
                        mma16816(c0, ah, bl0, bl1);
                        mma16816(c0, al, bh0, bh1);
                    }
                }
            }

            // ---- epilogue 1: gates -> h_tilde, write HT ----
            float ot[8], htl[8];
            #pragma unroll
            for (int nt = 0; nt < 2; nt++) {
                int i0 = nt*4;
                int kbase = (wk << 4) + nt*8 + (c4 << 1);
                float hts[4];
                #pragma unroll
                for (int rr = 0; rr < 4; rr++) {
                    int idx = i0 + rr;
                    int k   = kbase + (rr & 1);
                    float zi = zC[0][idx] + smf[F(OFF_BX) + (l*3 + 0)*128 + k];
                    float zo = zC[1][idx] + smf[F(OFF_BX) + (l*3 + 1)*128 + k];
                    float zc = zC[2][idx] + smf[F(OFF_BX) + (l*3 + 2)*128 + k];
                    float it = sig_f(zi);
                    ot[idx]  = sig_f(zo);
                    htl[idx] = tanh_f(zc) + it;
                    hts[rr]  = htl[idx];
                }
                uint32_t h01, l01, h23, l23;
                split2(hts[0], hts[1], h01, l01);
                split2(hts[2], hts[3], h23, l23);
                int row0 = g4 + wr*16, row1 = row0 + 8;
                *(uint32_t*)(sm + OFF_HTH + row0*HSTR + kbase*2) = h01;
                *(uint32_t*)(sm + OFF_HTL + row0*HSTR + kbase*2) = l01;
                *(uint32_t*)(sm + OFF_HTH + row1*HSTR + kbase*2) = h23;
                *(uint32_t*)(sm + OFF_HTL + row1*HSTR + kbase*2) = l23;
            }
            __syncthreads();

            // ---- Wd GEMM: this warp's m-tile, K=128 ----
            float zD[8];
            #pragma unroll
            for (int i = 0; i < 8; i++) zD[i] = 0.0f;
            const ull* wbL = g_wb + (size_t)l * 8192;
            #pragma unroll 2
            for (int kt = 0; kt < 8; kt++) {
                uint32_t hh[4], hl[4];
                ldm4(hh, smb + OFF_HTH + lmH + kt*32);
                ldm4(hl, smb + OFF_HTL + lmH + kt*32);
                #pragma unroll
                for (int nt = 0; nt < 2; nt++) {
                    int ntile = wk*2 + nt;
                    const ull* pb = wbL + ((size_t)kt*16 + ntile)*32 + lane;
                    ull vh = pb[0], vl = pb[4096];
                    uint32_t bh0 = (uint32_t)vh, bh1 = (uint32_t)(vh >> 32);
                    uint32_t bl0 = (uint32_t)vl, bl1 = (uint32_t)(vl >> 32);
                    mma16816(&zD[nt*4], hh, bh0, bh1);
                    mma16816(&zD[nt*4], hh, bl0, bl1);
                    mma16816(&zD[nt*4], hl, bh0, bh1);
                }
            }

            // ---- epilogue 2: recurrence, state update, write h operand ----
            float dec2[2], msk2[2];
            int lst2[2];
            #pragma unroll
            for (int q = 0; q < 2; q++) {
                int row = g4 + wr*16 + q*8;
                dec2[q] = smf[F(OFF_DEC) + row];
                msk2[q] = smf[F(OFF_MSK) + row];
                lst2[q] = lastArr[row];
            }
            #pragma unroll
            for (int nt = 0; nt < 2; nt++) {
                int i0 = nt*4;
                int kbase = (wk << 4) + nt*8 + (c4 << 1);
                float hvv[4];
                #pragma unroll
                for (int rr = 0; rr < 4; rr++) {
                    int idx = i0 + rr;
                    int q   = rr >> 1;
                    int k   = kbase + (rr & 1);
                    float hs    = tanh_f(zD[idx] + smf[F(OFF_BD) + l*128 + k]);
                    float dt    = sig_f(dec2[q] * smf[F(OFF_WT) + l*128 + k]
                                        + smf[F(OFF_BT) + l*128 + k]);
                    float hstar = (htl[idx] - hs) + hs * dt;
                    float cold  = cS[l][idx];
                    float cn    = tanh_f(hstar + ot[idx] * cold);
                    float hn    = ot[idx] * tanh_f(cn);
                    float m     = msk2[q];
                    float hv    = m * hn + (1.0f - m) * hS[l][idx];
                    float cv    = m * cn + (1.0f - m) * cold;
                    cS[l][idx] = cv;
                    hS[l][idx] = hv;
                    hvv[rr] = hv;
                    if (l == 1 && t == lst2[q])
                        smf[F(OFF_SV) + (g4 + wr*16 + (q << 3))*128 + k] = m * hv;
                }
                uint32_t h01, l01, h23, l23;
                split2(hvv[0], hvv[1], h01, l01);
                split2(hvv[2], hvv[3], h23, l23);
                int row0 = g4 + wr*16, row1 = row0 + 8;
                if (l == 0) {
                    *(uint32_t*)(sm + OFF_A1H + row0*ASTR + kbase*2) = h01;
                    *(uint32_t*)(sm + OFF_A1L + row0*ASTR + kbase*2) = l01;
                    *(uint32_t*)(sm + OFF_A1H + row1*ASTR + kbase*2) = h23;
                    *(uint32_t*)(sm + OFF_A1L + row1*ASTR + kbase*2) = l23;
                    *(uint32_t*)(sm + OFF_A0H + row0*ASTR + 256 + kbase*2) = h01;
                    *(uint32_t*)(sm + OFF_A0L + row0*ASTR + 256 + kbase*2) = l01;
                    *(uint32_t*)(sm + OFF_A0H + row1*ASTR + 256 + kbase*2) = h23;
                    *(uint32_t*)(sm + OFF_A0L + row1*ASTR + 256 + kbase*2) = l23;
                } else {
                    *(uint32_t*)(sm + OFF_A1H + row0*ASTR + 256 + kbase*2) = h01;
                    *(uint32_t*)(sm + OFF_A1L + row0*ASTR + 256 + kbase*2) = l01;
                    *(uint32_t*)(sm + OFF_A1H + row1*ASTR + 256 + kbase*2) = h23;
                    *(uint32_t*)(sm + OFF_A1L + row1*ASTR + 256 + kbase*2) = l23;
                }
            }
            __syncthreads();
        }
    }

    // ================= forecast head =================
    {
        int r = tid >> 4, d = tid & 15;
        smf[F(OFF_HISTB) + r*16 + d] =
            history[((size_t)(b0 + r) * Lh + lastArr[r]) * Dh + d];
    }
    __syncthreads();

    const unsigned FULL = 0xffffffffu;
    #pragma unroll
    for (int rr = 0; rr < 2; rr++) {
        const int r = w * 2 + rr;

        float s = 0.0f, s2 = 0.0f;
        for (int i = lane; i < HEAD_IN; i += 32) {
            float v = (i < 16) ? smf[F(OFF_HISTB) + r*16 + i]
                               : smf[F(OFF_SV) + r*128 + (i - 16)];
            s += v; s2 += v * v;
        }
        #pragma unroll
        for (int off = 16; off; off >>= 1) {
            s  += __shfl_xor_sync(FULL, s,  off);
            s2 += __shfl_xor_sync(FULL, s2, off);
        }
        float mean = s / (float)HEAD_IN;
        float var  = s2 / (float)HEAD_IN - mean * mean;
        float rstd = rsqrtf(var + 1e-5f);

        const int j0 = lane * 4;
        float4 acc = *reinterpret_cast<const float4*>(b1 + j0);
        for (int i = 0; i < HEAD_IN; i++) {
            float v  = (i < 16) ? smf[F(OFF_HISTB) + r*16 + i]
                                : smf[F(OFF_SV) + r*128 + (i - 16)];
            float sn = (v - mean) * rstd * ln_g[i] + ln_b[i];
            float4 w4 = *reinterpret_cast<const float4*>(W1 + i * Hh + j0);
            acc.x += sn * w4.x; acc.y += sn * w4.y;
            acc.z += sn * w4.z; acc.w += sn * w4.w;
        }
        float y[4] = { fmaxf(acc.x, 0.0f), fmaxf(acc.y, 0.0f),
                       fmaxf(acc.z, 0.0f), fmaxf(acc.w, 0.0f) };

        const int o0 = lane, o1 = lane + 32;
        float a0 = b2[o0];
        float a1 = (o1 < OUTD) ? b2[o1] : 0.0f;
        #pragma unroll
        for (int q = 0; q < 4; q++) {
            float yq = y[q];
            #pragma unroll 8
            for (int src = 0; src < 32; src++) {
                float v = __shfl_sync(FULL, yq, src);
                int   j = src * 4 + q;
                a0 += v * W2[j * OUTD + o0];
                if (o1 < OUTD) a1 += v * W2[j * OUTD + o1];
            }
        }
        size_t ob = (size_t)(b0 + r) * OUTD;
        out[ob + o0] = fixv(a0);
        if (o1 < OUTD) out[ob + o1] = fixv(a1);
    }
}

extern "C" void kernel_launch(void* const* d_in, const int* in_sizes, int n_in,
                              void* d_out, int out_size)
{
    const float* history = (const float*)d_in[0];
    const float* hmask   = (const float*)d_in[1];
    const float* Wp      = (const float*)d_in[2];
    const float* bp      = (const float*)d_in[3];
    const float* Wx      = (const float*)d_in[4];
    const float* bx      = (const float*)d_in[5];
    const float* Uh      = (const float*)d_in[6];
    const float* Wd      = (const float*)d_in[7];
    const float* bd      = (const float*)d_in[8];
    const float* Wt      = (const float*)d_in[9];
    const float* bt      = (const float*)d_in[10];
    const float* ln_g    = (const float*)d_in[11];
    const float* ln_b    = (const float*)d_in[12];
    const float* W1      = (const float*)d_in[13];
    const float* b1      = (const float*)d_in[14];
    const float* W2      = (const float*)d_in[15];
    const float* b2      = (const float*)d_in[16];

    pack_kernel<<<448, 256>>>(Wx, Uh, Wd);

    cudaFuncSetAttribute(tlstm_mma_kernel,
                         cudaFuncAttributeMaxDynamicSharedMemorySize, SMEM_TOTAL);
    tlstm_mma_kernel<<<CTAS, THREADS, SMEM_TOTAL>>>(
        history, hmask, Wp, bp, bx, bd, Wt, bt,
        ln_g, ln_b, W1, b1, W2, b2, (float*)d_out);
}

// round 12
// speedup vs baseline: 5.3020x; 1.6391x over previous
#include <cuda_runtime.h>
#include <cuda_fp16.h>
#include <math.h>
#include <stdint.h>

#define Lh    64
#define Dh    16
#define Hh    128
#define ROWS  32
#define THREADS 512
#define CTAS  128
#define HEAD_IN 144
#define OUTD  60

typedef unsigned long long ull;

// ---- SMEM layout (bytes). A images: 32 rows x 264 fp16 (stride 528B). HT: stride 272B.
#define OFF_A0    0
#define OFF_A1    16896
#define OFF_HT    33792
#define OFF_SV    42496
#define OFF_WP    58880
#define OFF_HISTB 67072
#define OFF_MSK   69120
#define OFF_DEC   69248
#define OFF_LAST  69376
#define OFF_BX    69504
#define OFF_BD    72576
#define OFF_WT    73600
#define OFF_BT    74624
#define OFF_BP    75648
#define SMEM_TOTAL 76160
#define F(off) ((off) >> 2)
#define ASTR 528
#define HSTR 272

// weight blobs in per-lane fragment order (fp16)
// gates: [l][kt(16)][ntile(48)][lane(32)] 8B ; ntile = gate*16 + wk*2 + nt
__device__ ull g_gb[2*16*48*32];
// Wd: [l][kt(8)][ntile(16)][lane(32)] 8B
__device__ ull g_wb[2*8*16*32];

__global__ void pack_kernel(const float* __restrict__ Wx,
                            const float* __restrict__ Uh,
                            const float* __restrict__ Wd)
{
    int idx = blockIdx.x * blockDim.x + threadIdx.x;
    if (idx < 49152) {
        int lane = idx & 31; int q = idx >> 5;
        int nt = q % 48; q /= 48;
        int kt = q & 15; int l = q >> 4;
        int gate = nt / 16;
        int n  = (nt % 16) * 8 + (lane >> 2);
        int kb = kt * 16 + (lane & 3) * 2;
        ull outv = 0;
        #pragma unroll
        for (int e = 0; e < 4; e++) {
            int kk = kb + (e & 1) + (e >> 1) * 8;   // kb, kb+1, kb+8, kb+9
            float v = (kk < 128)
                ? Wx[((size_t)(l*4 + gate + 1) * 128 + kk) * 128 + n]
                : Uh[((size_t)(l*4 + gate + 1) * 128 + (kk - 128)) * 128 + n];
            __half hv = __float2half_rn(v);
            outv |= (ull)(*(unsigned short*)&hv) << (16 * e);
        }
        g_gb[idx] = outv;
    } else if (idx < 49152 + 8192) {
        int i2 = idx - 49152;
        int lane = i2 & 31; int q = i2 >> 5;
        int nt = q & 15; q >>= 4;
        int kt = q & 7;  int l = q >> 3;
        int n  = nt * 8 + (lane >> 2);
        int kb = kt * 16 + (lane & 3) * 2;
        ull outv = 0;
        #pragma unroll
        for (int e = 0; e < 4; e++) {
            int kk = kb + (e & 1) + (e >> 1) * 8;
            float v = Wd[((size_t)l * 128 + kk) * 128 + n];
            __half hv = __float2half_rn(v);
            outv |= (ull)(*(unsigned short*)&hv) << (16 * e);
        }
        g_wb[i2] = outv;
    }
}

__device__ __forceinline__ uint32_t smem_u32(const void* p) {
    uint32_t a;
    asm("{ .reg .u64 t; cvta.to.shared.u64 t, %1; cvt.u32.u64 %0, t; }" : "=r"(a) : "l"(p));
    return a;
}
__device__ __forceinline__ void ldm4(uint32_t* r, uint32_t addr) {
    asm volatile("ldmatrix.sync.aligned.m8n8.x4.shared.b16 {%0,%1,%2,%3}, [%4];"
        : "=r"(r[0]), "=r"(r[1]), "=r"(r[2]), "=r"(r[3]) : "r"(addr));
}
__device__ __forceinline__ void mma16816(float* c, const uint32_t* a, uint32_t b0, uint32_t b1) {
    asm volatile("mma.sync.aligned.m16n8k16.row.col.f32.f16.f16.f32 "
        "{%0,%1,%2,%3}, {%4,%5,%6,%7}, {%8,%9}, {%0,%1,%2,%3};"
        : "+f"(c[0]), "+f"(c[1]), "+f"(c[2]), "+f"(c[3])
        : "r"(a[0]), "r"(a[1]), "r"(a[2]), "r"(a[3]), "r"(b0), "r"(b1));
}
__device__ __forceinline__ uint32_t packh2(float x, float y) {
    __half2 h = __floats2half2_rn(x, y);
    return *(uint32_t*)&h;
}
__device__ __forceinline__ float tanh_f(float x) {
    float e = __expf(2.0f * x);
    return 1.0f - __fdividef(2.0f, e + 1.0f);
}
__device__ __forceinline__ float sig_f(float x) {
    return __fdividef(1.0f, 1.0f + __expf(-x));
}
__device__ __forceinline__ float fixv(float x) {
    if (!(x == x)) return 0.0f;
    if (x > 1e38f) return 1e4f;
    if (x < -1e38f) return -1e4f;
    return x;
}

__global__ void __launch_bounds__(THREADS, 1)
tlstm_mma_kernel(const float* __restrict__ history, const float* __restrict__ hmask,
                 const float* __restrict__ Wp,  const float* __restrict__ bp,
                 const float* __restrict__ bx,  const float* __restrict__ bd,
                 const float* __restrict__ Wt,  const float* __restrict__ bt,
                 const float* __restrict__ ln_g, const float* __restrict__ ln_b,
                 const float* __restrict__ W1,  const float* __restrict__ b1,
                 const float* __restrict__ W2,  const float* __restrict__ b2,
                 float* __restrict__ out)
{
    extern __shared__ char sm[];
    float* smf = (float*)sm;
    int*   lastArr = (int*)(sm + OFF_LAST);
    const uint32_t smb = smem_u32(sm);

    const int tid  = threadIdx.x;
    const int b0   = blockIdx.x * ROWS;
    const int w    = tid >> 5;
    const int lane = tid & 31;
    const int wk   = w & 7;          // 8 k-warps: n-range [16wk, 16wk+16)
    const int wr   = w >> 3;         // 2 row groups: rows [16wr, 16wr+16)
    const int g4   = lane >> 2;
    const int c4   = lane & 3;

    // ldmatrix per-lane byte offsets within an image (this warp's m-tile)
    const int lm_row = (lane & 7) + ((lane >> 3) & 1) * 8 + wr * 16;
    const int lm_k8  = ((lane >> 4) & 1) * 8;
    const int lmA = lm_row * ASTR + lm_k8 * 2;
    const int lmH = lm_row * HSTR + lm_k8 * 2;

    // ---- init ----
    for (int i = tid; i < 33792 / 4; i += THREADS)   // zero A0,A1
        ((uint32_t*)sm)[i] = 0;
    for (int i = tid; i < Dh * Hh; i += THREADS)
        smf[F(OFF_WP) + i] = Wp[i];
    for (int i = tid; i < 768; i += THREADS) {       // bx: [l][gate(i,o,c)][k]
        int l = i / 384, gi = (i % 384) / 128, k = i & 127;
        smf[F(OFF_BX) + i] = bx[(l*4 + gi + 1)*128 + k];
    }
    if (tid < 256) smf[F(OFF_BD) + tid] = bd[tid];
    if (tid < 256) smf[F(OFF_WT) + tid] = Wt[tid];
    if (tid < 256) smf[F(OFF_BT) + tid] = bt[tid];
    if (tid < 128) smf[F(OFF_BP) + tid] = bp[tid];
    if (tid < ROWS) {
        const float* mp = hmask + (size_t)(b0 + tid) * Lh;
        float s = 0.0f;
        for (int t = 0; t < Lh; t++) s += mp[t];
        s = fminf(fmaxf(s, 1.0f), (float)Lh);
        lastArr[tid] = (int)s - 1;
    }
    __syncthreads();

    // per-lane register state: [layer][nt*4 + r]
    float cS[2][8], hS[2][8];
    #pragma unroll
    for (int l = 0; l < 2; l++)
        #pragma unroll
        for (int i = 0; i < 8; i++) { cS[l][i] = 0.0f; hS[l][i] = 0.0f; }

    // ================= time loop =================
    for (int t = 0; t < Lh; t++) {
        {
            int r = tid >> 4, d = tid & 15;    // 512 = 32 x 16
            smf[F(OFF_HISTB) + r*16 + d] = history[((size_t)(b0 + r) * Lh + t) * Dh + d];
        }
        if (tid < ROWS)
            smf[F(OFF_MSK) + tid] = hmask[(size_t)(b0 + tid) * Lh + t];
        __syncthreads();

        if (tid < ROWS) {
            float dd = fmaxf(smf[F(OFF_HISTB) + tid*16 + 5], 0.0f);
            smf[F(OFF_DEC) + tid] = 1.0f / logf(2.718281828459045f + dd);
        }
        // x = hist @ Wp + bp ; 32 rows x 16 threads, 8 channels per thread
        {
            int row = tid >> 4;
            int kb  = (tid & 15) * 8;
            float acc[8];
            #pragma unroll
            for (int ii = 0; ii < 8; ii++) acc[ii] = smf[F(OFF_BP) + kb + ii];
            #pragma unroll
            for (int d = 0; d < Dh; d++) {
                float hv = smf[F(OFF_HISTB) + row*16 + d];
                #pragma unroll
                for (int ii = 0; ii < 8; ii++)
                    acc[ii] += hv * smf[F(OFF_WP) + d*128 + kb + ii];
            }
            #pragma unroll
            for (int ii = 0; ii < 4; ii++)
                *(uint32_t*)(sm + OFF_A0 + row*ASTR + (kb + 2*ii)*2) =
                    packh2(acc[2*ii], acc[2*ii+1]);
        }
        __syncthreads();

        #pragma unroll
        for (int l = 0; l < 2; l++) {
            const uint32_t aB = smb + (l ? OFF_A1 : OFF_A0);

            // ---- gate GEMM: this warp's m-tile, n-range [16wk,16wk+16), K=256 ----
            float zC[3][8];
            #pragma unroll
            for (int gi = 0; gi < 3; gi++)
                #pragma unroll
                for (int i = 0; i < 8; i++) zC[gi][i] = 0.0f;

            const ull* gbL = g_gb + (size_t)l * 24576;
            #pragma unroll 4
            for (int kt = 0; kt < 16; kt++) {
                uint32_t a[4];
                ldm4(a, aB + lmA + kt*32);
                #pragma unroll
                for (int gi = 0; gi < 3; gi++) {
                    #pragma unroll
                    for (int nt = 0; nt < 2; nt++) {
                        int ntile = gi*16 + wk*2 + nt;
                        ull v = gbL[((size_t)kt*48 + ntile)*32 + lane];
                        mma16816(&zC[gi][nt*4], a, (uint32_t)v, (uint32_t)(v >> 32));
                    }
                }
            }

            // ---- epilogue 1: gates -> h_tilde, write HT ----
            float ot[8], htl[8];
            #pragma unroll
            for (int nt = 0; nt < 2; nt++) {
                int i0 = nt*4;
                int kbase = (wk << 4) + nt*8 + (c4 << 1);
                float hts[4];
                #pragma unroll
                for (int rr = 0; rr < 4; rr++) {
                    int idx = i0 + rr;
                    int k   = kbase + (rr & 1);
                    float zi = zC[0][idx] + smf[F(OFF_BX) + (l*3 + 0)*128 + k];
                    float zo = zC[1][idx] + smf[F(OFF_BX) + (l*3 + 1)*128 + k];
                    float zc = zC[2][idx] + smf[F(OFF_BX) + (l*3 + 2)*128 + k];
                    float it = sig_f(zi);
                    ot[idx]  = sig_f(zo);
                    htl[idx] = tanh_f(zc) + it;
                    hts[rr]  = htl[idx];
                }
                int row0 = g4 + wr*16, row1 = row0 + 8;
                *(uint32_t*)(sm + OFF_HT + row0*HSTR + kbase*2) = packh2(hts[0], hts[1]);
                *(uint32_t*)(sm + OFF_HT + row1*HSTR + kbase*2) = packh2(hts[2], hts[3]);
            }
            __syncthreads();

            // ---- Wd GEMM: this warp's m-tile, K=128 ----
            float zD[8];
            #pragma unroll
            for (int i = 0; i < 8; i++) zD[i] = 0.0f;
            const ull* wbL = g_wb + (size_t)l * 4096;
            #pragma unroll 4
            for (int kt = 0; kt < 8; kt++) {
                uint32_t hfr[4];
                ldm4(hfr, smb + OFF_HT + lmH + kt*32);
                #pragma unroll
                for (int nt = 0; nt < 2; nt++) {
                    int ntile = wk*2 + nt;
                    ull v = wbL[((size_t)kt*16 + ntile)*32 + lane];
                    mma16816(&zD[nt*4], hfr, (uint32_t)v, (uint32_t)(v >> 32));
                }
            }

            // ---- epilogue 2: recurrence, state update, write h operand ----
            float dec2[2], msk2[2];
            int lst2[2];
            #pragma unroll
            for (int q = 0; q < 2; q++) {
                int row = g4 + wr*16 + q*8;
                dec2[q] = smf[F(OFF_DEC) + row];
                msk2[q] = smf[F(OFF_MSK) + row];
                lst2[q] = lastArr[row];
            }
            #pragma unroll
            for (int nt = 0; nt < 2; nt++) {
                int i0 = nt*4;
                int kbase = (wk << 4) + nt*8 + (c4 << 1);
                float hvv[4];
                #pragma unroll
                for (int rr = 0; rr < 4; rr++) {
                    int idx = i0 + rr;
                    int q   = rr >> 1;
                    int k   = kbase + (rr & 1);
                    float hs    = tanh_f(zD[idx] + smf[F(OFF_BD) + l*128 + k]);
                    float dt    = sig_f(dec2[q] * smf[F(OFF_WT) + l*128 + k]
                                        + smf[F(OFF_BT) + l*128 + k]);
                    float hstar = (htl[idx] - hs) + hs * dt;
                    float cold  = cS[l][idx];
                    float cn    = tanh_f(hstar + ot[idx] * cold);
                    float hn    = ot[idx] * tanh_f(cn);
                    float m     = msk2[q];
                    float hv    = m * hn + (1.0f - m) * hS[l][idx];
                    float cv    = m * cn + (1.0f - m) * cold;
                    cS[l][idx] = cv;
                    hS[l][idx] = hv;
                    hvv[rr] = hv;
                    if (l == 1 && t == lst2[q])
                        smf[F(OFF_SV) + (g4 + wr*16 + (q << 3))*128 + k] = m * hv;
                }
                uint32_t p01 = packh2(hvv[0], hvv[1]);
                uint32_t p23 = packh2(hvv[2], hvv[3]);
                int row0 = g4 + wr*16, row1 = row0 + 8;
                if (l == 0) {
                    *(uint32_t*)(sm + OFF_A1 + row0*ASTR + kbase*2) = p01;
                    *(uint32_t*)(sm + OFF_A1 + row1*ASTR + kbase*2) = p23;
                    *(uint32_t*)(sm + OFF_A0 + row0*ASTR + 256 + kbase*2) = p01;
                    *(uint32_t*)(sm + OFF_A0 + row1*ASTR + 256 + kbase*2) = p23;
                } else {
                    *(uint32_t*)(sm + OFF_A1 + row0*ASTR + 256 + kbase*2) = p01;
                    *(uint32_t*)(sm + OFF_A1 + row1*ASTR + 256 + kbase*2) = p23;
                }
            }
            __syncthreads();
        }
    }

    // ================= forecast head =================
    {
        int r = tid >> 4, d = tid & 15;
        smf[F(OFF_HISTB) + r*16 + d] =
            history[((size_t)(b0 + r) * Lh + lastArr[r]) * Dh + d];
    }
    __syncthreads();

    const unsigned FULL = 0xffffffffu;
    #pragma unroll
    for (int rr = 0; rr < 2; rr++) {
        const int r = w * 2 + rr;

        float s = 0.0f, s2 = 0.0f;
        for (int i = lane; i < HEAD_IN; i += 32) {
            float v = (i < 16) ? smf[F(OFF_HISTB) + r*16 + i]
                               : smf[F(OFF_SV) + r*128 + (i - 16)];
            s += v; s2 += v * v;
        }
        #pragma unroll
        for (int off = 16; off; off >>= 1) {
            s  += __shfl_xor_sync(FULL, s,  off);
            s2 += __shfl_xor_sync(FULL, s2, off);
        }
        float mean = s / (float)HEAD_IN;
        float var  = s2 / (float)HEAD_IN - mean * mean;
        float rstd = rsqrtf(var + 1e-5f);

        const int j0 = lane * 4;
        float4 acc = *reinterpret_cast<const float4*>(b1 + j0);
        for (int i = 0; i < HEAD_IN; i++) {
            float v  = (i < 16) ? smf[F(OFF_HISTB) + r*16 + i]
                                : smf[F(OFF_SV) + r*128 + (i - 16)];
            float sn = (v - mean) * rstd * ln_g[i] + ln_b[i];
            float4 w4 = *reinterpret_cast<const float4*>(W1 + i * Hh + j0);
            acc.x += sn * w4.x; acc.y += sn * w4.y;
            acc.z += sn * w4.z; acc.w += sn * w4.w;
        }
        float y[4] = { fmaxf(acc.x, 0.0f), fmaxf(acc.y, 0.0f),
                       fmaxf(acc.z, 0.0f), fmaxf(acc.w, 0.0f) };

        const int o0 = lane, o1 = lane + 32;
        float a0 = b2[o0];
        float a1 = (o1 < OUTD) ? b2[o1] : 0.0f;
        #pragma unroll
        for (int q = 0; q < 4; q++) {
            float yq = y[q];
            #pragma unroll 8
            for (int src = 0; src < 32; src++) {
                float v = __shfl_sync(FULL, yq, src);
                int   j = src * 4 + q;
                a0 += v * W2[j * OUTD + o0];
                if (o1 < OUTD) a1 += v * W2[j * OUTD + o1];
            }
        }
        size_t ob = (size_t)(b0 + r) * OUTD;
        out[ob + o0] = fixv(a0);
        if (o1 < OUTD) out[ob + o1] = fixv(a1);
    }
}

extern "C" void kernel_launch(void* const* d_in, const int* in_sizes, int n_in,
                              void* d_out, int out_size)
{
    const float* history = (const float*)d_in[0];
    const float* hmask   = (const float*)d_in[1];
    const float* Wp      = (const float*)d_in[2];
    const float* bp      = (const float*)d_in[3];
    const float* Wx      = (const float*)d_in[4];
    const float* bx      = (const float*)d_in[5];
    const float* Uh      = (const float*)d_in[6];
    const float* Wd      = (const float*)d_in[7];
    const float* bd      = (const float*)d_in[8];
    const float* Wt      = (const float*)d_in[9];
    const float* bt      = (const float*)d_in[10];
    const float* ln_g    = (const float*)d_in[11];
    const float* ln_b    = (const float*)d_in[12];
    const float* W1      = (const float*)d_in[13];
    const float* b1      = (const float*)d_in[14];
    const float* W2      = (const float*)d_in[15];
    const float* b2      = (const float*)d_in[16];

    pack_kernel<<<224, 256>>>(Wx, Uh, Wd);

    cudaFuncSetAttribute(tlstm_mma_kernel,
                         cudaFuncAttributeMaxDynamicSharedMemorySize, SMEM_TOTAL);
    tlstm_mma_kernel<<<CTAS, THREADS, SMEM_TOTAL>>>(
        history, hmask, Wp, bp, bx, bd, Wt, bt,
        ln_g, ln_b, W1, b1, W2, b2, (float*)d_out);
}

// round 13
// speedup vs baseline: 6.3529x; 1.1982x over previous
#include <cuda_runtime.h>
#include <cuda_fp16.h>
#include <math.h>
#include <stdint.h>

#define Lh    64
#define Dh    16
#define Hh    128
#define ROWS  32
#define THREADS 512
#define CTAS  128
#define HEAD_IN 144
#define OUTD  60

typedef unsigned long long ull;

// ---- SMEM layout (bytes). A images: 32 rows x 264 fp16 (stride 528B). HT: stride 272B.
#define OFF_A0    0
#define OFF_A1    16896
#define OFF_HT    33792
#define OFF_SV    42496
#define OFF_WP    58880
#define OFF_HISTB 67072
#define OFF_MSK   69120
#define OFF_DEC   69248
#define OFF_LAST  69376
#define OFF_BX    69504
#define OFF_BD    72576
#define OFF_WT    73600
#define OFF_BT    74624
#define OFF_BP    75648
#define SMEM_TOTAL 76160
#define F(off) ((off) >> 2)
#define ASTR 528
#define HSTR 272

// weight blobs, fp16, n-tile PAIRS adjacent per lane for LDG.128:
// gates: [l][kt(16)][gi(3)*8 + wk(8)][lane(32)][pair(2)] 8B each
__device__ ull g_gb[2*16*24*32*2];
// Wd: [l][kt(8)][wk(8)][lane(32)][pair(2)]
__device__ ull g_wb[2*8*8*32*2];

__global__ void pack_kernel(const float* __restrict__ Wx,
                            const float* __restrict__ Uh,
                            const float* __restrict__ Wd)
{
    int idx = blockIdx.x * blockDim.x + threadIdx.x;   // one ull each
    if (idx < 49152) {
        int pr   = idx & 1;
        int lane = (idx >> 1) & 31;
        int q    = idx >> 6;
        int gw   = q % 24; q /= 24;
        int kt   = q & 15; int l = q >> 4;
        int gate = gw >> 3;
        int wk   = gw & 7;
        int ntile = gate * 16 + wk * 2 + pr;
        int n  = (ntile % 16) * 8 + (lane >> 2);
        int kb = kt * 16 + (lane & 3) * 2;
        ull outv = 0;
        #pragma unroll
        for (int e = 0; e < 4; e++) {
            int kk = kb + (e & 1) + (e >> 1) * 8;   // kb, kb+1, kb+8, kb+9
            float v = (kk < 128)
                ? Wx[((size_t)(l*4 + gate + 1) * 128 + kk) * 128 + n]
                : Uh[((size_t)(l*4 + gate + 1) * 128 + (kk - 128)) * 128 + n];
            __half hv = __float2half_rn(v);
            outv |= (ull)(*(unsigned short*)&hv) << (16 * e);
        }
        g_gb[idx] = outv;
    } else if (idx < 49152 + 8192) {
        int i2   = idx - 49152;
        int pr   = i2 & 1;
        int lane = (i2 >> 1) & 31;
        int q    = i2 >> 6;
        int wk   = q & 7; q >>= 3;
        int kt   = q & 7; int l = q >> 3;
        int ntile = wk * 2 + pr;
        int n  = ntile * 8 + (lane >> 2);
        int kb = kt * 16 + (lane & 3) * 2;
        ull outv = 0;
        #pragma unroll
        for (int e = 0; e < 4; e++) {
            int kk = kb + (e & 1) + (e >> 1) * 8;
            float v = Wd[((size_t)l * 128 + kk) * 128 + n];
            __half hv = __float2half_rn(v);
            outv |= (ull)(*(unsigned short*)&hv) << (16 * e);
        }
        g_wb[i2] = outv;
    }
}

__device__ __forceinline__ uint32_t smem_u32(const void* p) {
    uint32_t a;
    asm("{ .reg .u64 t; cvta.to.shared.u64 t, %1; cvt.u32.u64 %0, t; }" : "=r"(a) : "l"(p));
    return a;
}
__device__ __forceinline__ void ldm4(uint32_t* r, uint32_t addr) {
    asm volatile("ldmatrix.sync.aligned.m8n8.x4.shared.b16 {%0,%1,%2,%3}, [%4];"
        : "=r"(r[0]), "=r"(r[1]), "=r"(r[2]), "=r"(r[3]) : "r"(addr));
}
__device__ __forceinline__ void mma16816(float* c, const uint32_t* a, uint32_t b0, uint32_t b1) {
    asm volatile("mma.sync.aligned.m16n8k16.row.col.f32.f16.f16.f32 "
        "{%0,%1,%2,%3}, {%4,%5,%6,%7}, {%8,%9}, {%0,%1,%2,%3};"
        : "+f"(c[0]), "+f"(c[1]), "+f"(c[2]), "+f"(c[3])
        : "r"(a[0]), "r"(a[1]), "r"(a[2]), "r"(a[3]), "r"(b0), "r"(b1));
}
__device__ __forceinline__ uint32_t packh2(float x, float y) {
    __half2 h = __floats2half2_rn(x, y);
    return *(uint32_t*)&h;
}
// single-MUFU transcendentals (tanh.approx, sm_75+; legal in baseline PTX)
__device__ __forceinline__ float tanh_f(float x) {
    float r;
    asm("tanh.approx.f32 %0, %1;" : "=f"(r) : "f"(x));
    return r;
}
__device__ __forceinline__ float sig_f(float x) {
    return fmaf(0.5f, tanh_f(0.5f * x), 0.5f);
}
__device__ __forceinline__ float fixv(float x) {
    if (!(x == x)) return 0.0f;
    if (x > 1e38f) return 1e4f;
    if (x < -1e38f) return -1e4f;
    return x;
}

__global__ void __launch_bounds__(THREADS, 1)
tlstm_mma_kernel(const float* __restrict__ history, const float* __restrict__ hmask,
                 const float* __restrict__ Wp,  const float* __restrict__ bp,
                 const float* __restrict__ bx,  const float* __restrict__ bd,
                 const float* __restrict__ Wt,  const float* __restrict__ bt,
                 const float* __restrict__ ln_g, const float* __restrict__ ln_b,
                 const float* __restrict__ W1,  const float* __restrict__ b1,
                 const float* __restrict__ W2,  const float* __restrict__ b2,
                 float* __restrict__ out)
{
    extern __shared__ char sm[];
    float* smf = (float*)sm;
    int*   lastArr = (int*)(sm + OFF_LAST);
    const uint32_t smb = smem_u32(sm);

    const int tid  = threadIdx.x;
    const int b0   = blockIdx.x * ROWS;
    const int w    = tid >> 5;
    const int lane = tid & 31;
    const int wk   = w & 7;          // 8 k-warps: n-range [16wk, 16wk+16)
    const int wr   = w >> 3;         // 2 row groups: rows [16wr, 16wr+16)
    const int g4   = lane >> 2;
    const int c4   = lane & 3;

    // ldmatrix per-lane byte offsets within an image (this warp's m-tile)
    const int lm_row = (lane & 7) + ((lane >> 3) & 1) * 8 + wr * 16;
    const int lm_k8  = ((lane >> 4) & 1) * 8;
    const int lmA = lm_row * ASTR + lm_k8 * 2;
    const int lmH = lm_row * HSTR + lm_k8 * 2;

    // ---- init ----
    for (int i = tid; i < 33792 / 4; i += THREADS)   // zero A0,A1
        ((uint32_t*)sm)[i] = 0;
    for (int i = tid; i < Dh * Hh; i += THREADS)
        smf[F(OFF_WP) + i] = Wp[i];
    for (int i = tid; i < 768; i += THREADS) {       // bx: [l][gate(i,o,c)][k]
        int l = i / 384, gi = (i % 384) / 128, k = i & 127;
        smf[F(OFF_BX) + i] = bx[(l*4 + gi + 1)*128 + k];
    }
    if (tid < 256) smf[F(OFF_BD) + tid] = bd[tid];
    if (tid < 256) smf[F(OFF_WT) + tid] = Wt[tid];
    if (tid < 256) smf[F(OFF_BT) + tid] = bt[tid];
    if (tid < 128) smf[F(OFF_BP) + tid] = bp[tid];
    if (tid < ROWS) {
        const float* mp = hmask + (size_t)(b0 + tid) * Lh;
        float s = 0.0f;
        for (int t = 0; t < Lh; t++) s += mp[t];
        s = fminf(fmaxf(s, 1.0f), (float)Lh);
        lastArr[tid] = (int)s - 1;
    }
    __syncthreads();

    // per-lane register state: [layer][nt*4 + r]
    float cS[2][8], hS[2][8];
    #pragma unroll
    for (int l = 0; l < 2; l++)
        #pragma unroll
        for (int i = 0; i < 8; i++) { cS[l][i] = 0.0f; hS[l][i] = 0.0f; }

    // ================= time loop =================
    for (int t = 0; t < Lh; t++) {
        {
            int r = tid >> 4, d = tid & 15;    // 512 = 32 x 16
            smf[F(OFF_HISTB) + r*16 + d] = history[((size_t)(b0 + r) * Lh + t) * Dh + d];
        }
        if (tid < ROWS)
            smf[F(OFF_MSK) + tid] = hmask[(size_t)(b0 + tid) * Lh + t];
        __syncthreads();

        if (tid < ROWS) {
            float dd = fmaxf(smf[F(OFF_HISTB) + tid*16 + 5], 0.0f);
            smf[F(OFF_DEC) + tid] = 1.0f / logf(2.718281828459045f + dd);
        }
        // x = hist @ Wp + bp ; 32 rows x 16 threads, 8 channels per thread
        {
            int row = tid >> 4;
            int kb  = (tid & 15) * 8;
            float acc[8];
            #pragma unroll
            for (int ii = 0; ii < 8; ii++) acc[ii] = smf[F(OFF_BP) + kb + ii];
            #pragma unroll
            for (int d = 0; d < Dh; d++) {
                float hv = smf[F(OFF_HISTB) + row*16 + d];
                #pragma unroll
                for (int ii = 0; ii < 8; ii++)
                    acc[ii] += hv * smf[F(OFF_WP) + d*128 + kb + ii];
            }
            #pragma unroll
            for (int ii = 0; ii < 4; ii++)
                *(uint32_t*)(sm + OFF_A0 + row*ASTR + (kb + 2*ii)*2) =
                    packh2(acc[2*ii], acc[2*ii+1]);
        }
        __syncthreads();

        #pragma unroll
        for (int l = 0; l < 2; l++) {
            const uint32_t aB = smb + (l ? OFF_A1 : OFF_A0);

            // ---- gate GEMM: this warp's m-tile, n-range [16wk,16wk+16), K=256 ----
            float zC[3][8];
            #pragma unroll
            for (int gi = 0; gi < 3; gi++)
                #pragma unroll
                for (int i = 0; i < 8; i++) zC[gi][i] = 0.0f;

            const ull* gbL = g_gb + (size_t)l * 24576;
            #pragma unroll 4
            for (int kt = 0; kt < 16; kt++) {
                uint32_t a[4];
                ldm4(a, aB + lmA + kt*32);
                #pragma unroll
                for (int gi = 0; gi < 3; gi++) {
                    // one LDG.128 delivers both n-tiles for this (kt, gi)
                    ulonglong2 v = *(const ulonglong2*)
                        (gbL + (((size_t)kt*24 + gi*8 + wk) << 6) + lane*2);
                    mma16816(&zC[gi][0], a, (uint32_t)v.x, (uint32_t)(v.x >> 32));
                    mma16816(&zC[gi][4], a, (uint32_t)v.y, (uint32_t)(v.y >> 32));
                }
            }

            // ---- epilogue 1: gates -> h_tilde, write HT ----
            float ot[8], htl[8];
            #pragma unroll
            for (int nt = 0; nt < 2; nt++) {
                int i0 = nt*4;
                int kbase = (wk << 4) + nt*8 + (c4 << 1);
                float hts[4];
                #pragma unroll
                for (int rr = 0; rr < 4; rr++) {
                    int idx = i0 + rr;
                    int k   = kbase + (rr & 1);
                    float zi = zC[0][idx] + smf[F(OFF_BX) + (l*3 + 0)*128 + k];
                    float zo = zC[1][idx] + smf[F(OFF_BX) + (l*3 + 1)*128 + k];
                    float zc = zC[2][idx] + smf[F(OFF_BX) + (l*3 + 2)*128 + k];
                    float it = sig_f(zi);
                    ot[idx]  = sig_f(zo);
                    htl[idx] = tanh_f(zc) + it;
                    hts[rr]  = htl[idx];
                }
                int row0 = g4 + wr*16, row1 = row0 + 8;
                *(uint32_t*)(sm + OFF_HT + row0*HSTR + kbase*2) = packh2(hts[0], hts[1]);
                *(uint32_t*)(sm + OFF_HT + row1*HSTR + kbase*2) = packh2(hts[2], hts[3]);
            }
            __syncthreads();

            // ---- Wd GEMM: this warp's m-tile, K=128 ----
            float zD[8];
            #pragma unroll
            for (int i = 0; i < 8; i++) zD[i] = 0.0f;
            const ull* wbL = g_wb + (size_t)l * 4096;
            #pragma unroll 4
            for (int kt = 0; kt < 8; kt++) {
                uint32_t hfr[4];
                ldm4(hfr, smb + OFF_HT + lmH + kt*32);
                ulonglong2 v = *(const ulonglong2*)
                    (wbL + (((size_t)kt*8 + wk) << 6) + lane*2);
                mma16816(&zD[0], hfr, (uint32_t)v.x, (uint32_t)(v.x >> 32));
                mma16816(&zD[4], hfr, (uint32_t)v.y, (uint32_t)(v.y >> 32));
            }

            // ---- epilogue 2: recurrence, state update, write h operand ----
            float dec2[2], msk2[2];
            int lst2[2];
            #pragma unroll
            for (int q = 0; q < 2; q++) {
                int row = g4 + wr*16 + q*8;
                dec2[q] = smf[F(OFF_DEC) + row];
                msk2[q] = smf[F(OFF_MSK) + row];
                lst2[q] = lastArr[row];
            }
            #pragma unroll
            for (int nt = 0; nt < 2; nt++) {
                int i0 = nt*4;
                int kbase = (wk << 4) + nt*8 + (c4 << 1);
                float hvv[4];
                #pragma unroll
                for (int rr = 0; rr < 4; rr++) {
                    int idx = i0 + rr;
                    int q   = rr >> 1;
                    int k   = kbase + (rr & 1);
                    float hs    = tanh_f(zD[idx] + smf[F(OFF_BD) + l*128 + k]);
                    float dt    = sig_f(dec2[q] * smf[F(OFF_WT) + l*128 + k]
                                        + smf[F(OFF_BT) + l*128 + k]);
                    float hstar = (htl[idx] - hs) + hs * dt;
                    float cold  = cS[l][idx];
                    float cn    = tanh_f(hstar + ot[idx] * cold);
                    float hn    = ot[idx] * tanh_f(cn);
                    float m     = msk2[q];
                    float hv    = m * hn + (1.0f - m) * hS[l][idx];
                    float cv    = m * cn + (1.0f - m) * cold;
                    cS[l][idx] = cv;
                    hS[l][idx] = hv;
                    hvv[rr] = hv;
                    if (l == 1 && t == lst2[q])
                        smf[F(OFF_SV) + (g4 + wr*16 + (q << 3))*128 + k] = m * hv;
                }
                uint32_t p01 = packh2(hvv[0], hvv[1]);
                uint32_t p23 = packh2(hvv[2], hvv[3]);
                int row0 = g4 + wr*16, row1 = row0 + 8;
                if (l == 0) {
                    *(uint32_t*)(sm + OFF_A1 + row0*ASTR + kbase*2) = p01;
                    *(uint32_t*)(sm + OFF_A1 + row1*ASTR + kbase*2) = p23;
                    *(uint32_t*)(sm + OFF_A0 + row0*ASTR + 256 + kbase*2) = p01;
                    *(uint32_t*)(sm + OFF_A0 + row1*ASTR + 256 + kbase*2) = p23;
                } else {
                    *(uint32_t*)(sm + OFF_A1 + row0*ASTR + 256 + kbase*2) = p01;
                    *(uint32_t*)(sm + OFF_A1 + row1*ASTR + 256 + kbase*2) = p23;
                }
            }
            __syncthreads();
        }
    }

    // ================= forecast head =================
    {
        int r = tid >> 4, d = tid & 15;
        smf[F(OFF_HISTB) + r*16 + d] =
            history[((size_t)(b0 + r) * Lh + lastArr[r]) * Dh + d];
    }
    __syncthreads();

    const unsigned FULL = 0xffffffffu;
    #pragma unroll
    for (int rr = 0; rr < 2; rr++) {
        const int r = w * 2 + rr;

        float s = 0.0f, s2 = 0.0f;
        for (int i = lane; i < HEAD_IN; i += 32) {
            float v = (i < 16) ? smf[F(OFF_HISTB) + r*16 + i]
                               : smf[F(OFF_SV) + r*128 + (i - 16)];
            s += v; s2 += v * v;
        }
        #pragma unroll
        for (int off = 16; off; off >>= 1) {
            s  += __shfl_xor_sync(FULL, s,  off);
            s2 += __shfl_xor_sync(FULL, s2, off);
        }
        float mean = s / (float)HEAD_IN;
        float var  = s2 / (float)HEAD_IN - mean * mean;
        float rstd = rsqrtf(var + 1e-5f);

        const int j0 = lane * 4;
        float4 acc = *reinterpret_cast<const float4*>(b1 + j0);
        for (int i = 0; i < HEAD_IN; i++) {
            float v  = (i < 16) ? smf[F(OFF_HISTB) + r*16 + i]
                                : smf[F(OFF_SV) + r*128 + (i - 16)];
            float sn = (v - mean) * rstd * ln_g[i] + ln_b[i];
            float4 w4 = *reinterpret_cast<const float4*>(W1 + i * Hh + j0);
            acc.x += sn * w4.x; acc.y += sn * w4.y;
            acc.z += sn * w4.z; acc.w += sn * w4.w;
        }
        float y[4] = { fmaxf(acc.x, 0.0f), fmaxf(acc.y, 0.0f),
                       fmaxf(acc.z, 0.0f), fmaxf(acc.w, 0.0f) };

        const int o0 = lane, o1 = lane + 32;
        float a0 = b2[o0];
        float a1 = (o1 < OUTD) ? b2[o1] : 0.0f;
        #pragma unroll
        for (int q = 0; q < 4; q++) {
            float yq = y[q];
            #pragma unroll 8
            for (int src = 0; src < 32; src++) {
                float v = __shfl_sync(FULL, yq, src);
                int   j = src * 4 + q;
                a0 += v * W2[j * OUTD + o0];
                if (o1 < OUTD) a1 += v * W2[j * OUTD + o1];
            }
        }
        size_t ob = (size_t)(b0 + r) * OUTD;
        out[ob + o0] = fixv(a0);
        if (o1 < OUTD) out[ob + o1] = fixv(a1);
    }
}

extern "C" void kernel_launch(void* const* d_in, const int* in_sizes, int n_in,
                              void* d_out, int out_size)
{
    const float* history = (const float*)d_in[0];
    const float* hmask   = (const float*)d_in[1];
    const float* Wp      = (const float*)d_in[2];
    const float* bp      = (const float*)d_in[3];
    const float* Wx      = (const float*)d_in[4];
    const float* bx      = (const float*)d_in[5];
    const float* Uh      = (const float*)d_in[6];
    const float* Wd      = (const float*)d_in[7];
    const float* bd      = (const float*)d_in[8];
    const float* Wt      = (const float*)d_in[9];
    const float* bt      = (const float*)d_in[10];
    const float* ln_g    = (const float*)d_in[11];
    const float* ln_b    = (const float*)d_in[12];
    const float* W1      = (const float*)d_in[13];
    const float* b1      = (const float*)d_in[14];
    const float* W2      = (const float*)d_in[15];
    const float* b2      = (const float*)d_in[16];

    pack_kernel<<<225, 256>>>(Wx, Uh, Wd);

    cudaFuncSetAttribute(tlstm_mma_kernel,
                         cudaFuncAttributeMaxDynamicSharedMemorySize, SMEM_TOTAL);
    tlstm_mma_kernel<<<CTAS, THREADS, SMEM_TOTAL>>>(
        history, hmask, Wp, bp, bx, bd, Wt, bt,
        ln_g, ln_b, W1, b1, W2, b2, (float*)d_out);
}

// round 14
// speedup vs baseline: 6.5031x; 1.0237x over previous
#include <cuda_runtime.h>
#include <cuda_fp16.h>
#include <math.h>
#include <stdint.h>

#define Lh    64
#define Dh    16
#define Hh    128
#define ROWS  32
#define THREADS 512
#define CTAS  128
#define HEAD_IN 144
#define OUTD  60

typedef unsigned long long ull;

// ---- SMEM layout (bytes). A images: 32 rows x 264 fp16 (stride 528B). HT: stride 272B.
#define OFF_A0    0
#define OFF_A1    16896
#define OFF_HT    33792
#define OFF_SV    42496
#define OFF_WP    58880
#define OFF_HISTB 67072
#define OFF_MSK   69120
#define OFF_DEC   69248
#define OFF_LAST  69376
#define OFF_BX    69504
#define OFF_BD    72576
#define OFF_WT    73600
#define OFF_BT    74624
#define OFF_BP    75648
#define SMEM_TOTAL 76160
#define F(off) ((off) >> 2)
#define ASTR 528
#define HSTR 272

// weight blobs, fp16, stored ONCE (no wr duplication):
// gates: [l][kt(16)][gi(3)][w(16)][lane(32)] 8B frags  (strides: l 24576, kt 1536, gi 512, w 32)
__device__ ull g_gb[2*16*3*16*32];
// Wd: [l][kt(8)][w(16)][lane(32)]                       (strides: l 4096, kt 512, w 32)
__device__ ull g_wb[2*8*16*32];

__global__ void pack_kernel(const float* __restrict__ Wx,
                            const float* __restrict__ Uh,
                            const float* __restrict__ Wd)
{
    int idx = blockIdx.x * blockDim.x + threadIdx.x;
    if (idx < 49152) {
        int l  = idx / 24576;
        int r  = idx % 24576;
        int kt = r / 1536;  r %= 1536;
        int gi = r / 512;   r %= 512;
        int w  = r / 32;
        int lane = r % 32;
        int n  = w * 8 + (lane >> 2);
        int kb = kt * 16 + (lane & 3) * 2;
        ull outv = 0;
        #pragma unroll
        for (int e = 0; e < 4; e++) {
            int kk = kb + (e & 1) + (e >> 1) * 8;   // kb, kb+1, kb+8, kb+9
            float v = (kk < 128)
                ? Wx[((size_t)(l*4 + gi + 1) * 128 + kk) * 128 + n]
                : Uh[((size_t)(l*4 + gi + 1) * 128 + (kk - 128)) * 128 + n];
            __half hv = __float2half_rn(v);
            outv |= (ull)(*(unsigned short*)&hv) << (16 * e);
        }
        g_gb[idx] = outv;
    } else if (idx < 49152 + 8192) {
        int i2 = idx - 49152;
        int l  = i2 / 4096;
        int r  = i2 % 4096;
        int kt = r / 512;  r %= 512;
        int w  = r / 32;
        int lane = r % 32;
        int n  = w * 8 + (lane >> 2);
        int kb = kt * 16 + (lane & 3) * 2;
        ull outv = 0;
        #pragma unroll
        for (int e = 0; e < 4; e++) {
            int kk = kb + (e & 1) + (e >> 1) * 8;
            float v = Wd[((size_t)l * 128 + kk) * 128 + n];
            __half hv = __float2half_rn(v);
            outv |= (ull)(*(unsigned short*)&hv) << (16 * e);
        }
        g_wb[i2] = outv;
    }
}

__device__ __forceinline__ uint32_t smem_u32(const void* p) {
    uint32_t a;
    asm("{ .reg .u64 t; cvta.to.shared.u64 t, %1; cvt.u32.u64 %0, t; }" : "=r"(a) : "l"(p));
    return a;
}
__device__ __forceinline__ void ldm4(uint32_t* r, uint32_t addr) {
    asm volatile("ldmatrix.sync.aligned.m8n8.x4.shared.b16 {%0,%1,%2,%3}, [%4];"
        : "=r"(r[0]), "=r"(r[1]), "=r"(r[2]), "=r"(r[3]) : "r"(addr));
}
__device__ __forceinline__ void mma16816(float* c, const uint32_t* a, uint32_t b0, uint32_t b1) {
    asm volatile("mma.sync.aligned.m16n8k16.row.col.f32.f16.f16.f32 "
        "{%0,%1,%2,%3}, {%4,%5,%6,%7}, {%8,%9}, {%0,%1,%2,%3};"
        : "+f"(c[0]), "+f"(c[1]), "+f"(c[2]), "+f"(c[3])
        : "r"(a[0]), "r"(a[1]), "r"(a[2]), "r"(a[3]), "r"(b0), "r"(b1));
}
__device__ __forceinline__ uint32_t packh2(float x, float y) {
    __half2 h = __floats2half2_rn(x, y);
    return *(uint32_t*)&h;
}
__device__ __forceinline__ float tanh_f(float x) {
    float r;
    asm("tanh.approx.f32 %0, %1;" : "=f"(r) : "f"(x));
    return r;
}
__device__ __forceinline__ float sig_f(float x) {
    return fmaf(0.5f, tanh_f(0.5f * x), 0.5f);
}
__device__ __forceinline__ float fixv(float x) {
    if (!(x == x)) return 0.0f;
    if (x > 1e38f) return 1e4f;
    if (x < -1e38f) return -1e4f;
    return x;
}

__global__ void __launch_bounds__(THREADS, 1)
tlstm_mma_kernel(const float* __restrict__ history, const float* __restrict__ hmask,
                 const float* __restrict__ Wp,  const float* __restrict__ bp,
                 const float* __restrict__ bx,  const float* __restrict__ bd,
                 const float* __restrict__ Wt,  const float* __restrict__ bt,
                 const float* __restrict__ ln_g, const float* __restrict__ ln_b,
                 const float* __restrict__ W1,  const float* __restrict__ b1,
                 const float* __restrict__ W2,  const float* __restrict__ b2,
                 float* __restrict__ out)
{
    extern __shared__ char sm[];
    float* smf = (float*)sm;
    int*   lastArr = (int*)(sm + OFF_LAST);
    const uint32_t smb = smem_u32(sm);

    const int tid  = threadIdx.x;
    const int b0   = blockIdx.x * ROWS;
    const int w    = tid >> 5;       // 16 warps: n-tile [8w, 8w+8) per gate, full M=32
    const int lane = tid & 31;
    const int g4   = lane >> 2;
    const int c4   = lane & 3;
    const int kbase = w * 8 + c4 * 2;   // this lane's 2 k-channels: kbase, kbase+1

    // ldmatrix per-lane byte offsets (two m-tiles)
    const int lm_row = (lane & 7) + ((lane >> 3) & 1) * 8;
    const int lm_k8  = ((lane >> 4) & 1) * 8;
    const int lmA0 = lm_row * ASTR + lm_k8 * 2;
    const int lmA1 = (lm_row + 16) * ASTR + lm_k8 * 2;
    const int lmH0 = lm_row * HSTR + lm_k8 * 2;
    const int lmH1 = (lm_row + 16) * HSTR + lm_k8 * 2;

    // ---- init ----
    for (int i = tid; i < 33792 / 4; i += THREADS)   // zero A0,A1
        ((uint32_t*)sm)[i] = 0;
    for (int i = tid; i < Dh * Hh; i += THREADS)
        smf[F(OFF_WP) + i] = Wp[i];
    for (int i = tid; i < 768; i += THREADS) {       // bx: [l][gate(i,o,c)][k]
        int l = i / 384, gi = (i % 384) / 128, k = i & 127;
        smf[F(OFF_BX) + i] = bx[(l*4 + gi + 1)*128 + k];
    }
    if (tid < 256) smf[F(OFF_BD) + tid] = bd[tid];
    if (tid < 256) smf[F(OFF_WT) + tid] = Wt[tid];
    if (tid < 256) smf[F(OFF_BT) + tid] = bt[tid];
    if (tid < 128) smf[F(OFF_BP) + tid] = bp[tid];
    if (tid < ROWS) {
        const float* mp = hmask + (size_t)(b0 + tid) * Lh;
        float s = 0.0f;
        for (int t = 0; t < Lh; t++) s += mp[t];
        s = fminf(fmaxf(s, 1.0f), (float)Lh);
        lastArr[tid] = (int)s - 1;
    }
    __syncthreads();

    // per-lane state: idx = mt*4 + rr; row = g4 + mt*16 + (rr>>1)*8; k = kbase + (rr&1)
    float cS[2][8], hS[2][8];
    #pragma unroll
    for (int l = 0; l < 2; l++)
        #pragma unroll
        for (int i = 0; i < 8; i++) { cS[l][i] = 0.0f; hS[l][i] = 0.0f; }

    // ================= time loop =================
    for (int t = 0; t < Lh; t++) {
        {
            int r = tid >> 4, d = tid & 15;    // 512 = 32 x 16
            smf[F(OFF_HISTB) + r*16 + d] = history[((size_t)(b0 + r) * Lh + t) * Dh + d];
        }
        if (tid < ROWS)
            smf[F(OFF_MSK) + tid] = hmask[(size_t)(b0 + tid) * Lh + t];
        __syncthreads();

        if (tid < ROWS) {
            float dd = fmaxf(smf[F(OFF_HISTB) + tid*16 + 5], 0.0f);
            smf[F(OFF_DEC) + tid] = 1.0f / logf(2.718281828459045f + dd);
        }
        // x = hist @ Wp + bp ; 32 rows x 16 threads, 8 channels per thread
        {
            int row = tid >> 4;
            int kb  = (tid & 15) * 8;
            float acc[8];
            #pragma unroll
            for (int ii = 0; ii < 8; ii++) acc[ii] = smf[F(OFF_BP) + kb + ii];
            #pragma unroll
            for (int d = 0; d < Dh; d++) {
                float hv = smf[F(OFF_HISTB) + row*16 + d];
                #pragma unroll
                for (int ii = 0; ii < 8; ii++)
                    acc[ii] += hv * smf[F(OFF_WP) + d*128 + kb + ii];
            }
            #pragma unroll
            for (int ii = 0; ii < 4; ii++)
                *(uint32_t*)(sm + OFF_A0 + row*ASTR + (kb + 2*ii)*2) =
                    packh2(acc[2*ii], acc[2*ii+1]);
        }
        __syncthreads();

        #pragma unroll
        for (int l = 0; l < 2; l++) {
            const uint32_t aB = smb + (l ? OFF_A1 : OFF_A0);

            // ---- gate GEMM: M=32 (2 m-tiles), n-tile w per gate, K=256 ----
            float zC[3][8];
            #pragma unroll
            for (int gi = 0; gi < 3; gi++)
                #pragma unroll
                for (int i = 0; i < 8; i++) zC[gi][i] = 0.0f;

            const ull* gbW = g_gb + (size_t)l * 24576 + w*32 + lane;
            // prefetch kt=0 fragments
            ull wb0 = gbW[0];
            ull wb1 = gbW[512];
            ull wb2 = gbW[1024];
            #pragma unroll 4
            for (int kt = 0; kt < 16; kt++) {
                uint32_t a0[4], a1[4];
                ldm4(a0, aB + lmA0 + kt*32);
                ldm4(a1, aB + lmA1 + kt*32);
                ull w0 = wb0, w1 = wb1, w2 = wb2;
                if (kt < 15) {
                    const ull* nx = gbW + (kt + 1) * 1536;
                    wb0 = nx[0]; wb1 = nx[512]; wb2 = nx[1024];
                }
                mma16816(&zC[0][0], a0, (uint32_t)w0, (uint32_t)(w0 >> 32));
                mma16816(&zC[0][4], a1, (uint32_t)w0, (uint32_t)(w0 >> 32));
                mma16816(&zC[1][0], a0, (uint32_t)w1, (uint32_t)(w1 >> 32));
                mma16816(&zC[1][4], a1, (uint32_t)w1, (uint32_t)(w1 >> 32));
                mma16816(&zC[2][0], a0, (uint32_t)w2, (uint32_t)(w2 >> 32));
                mma16816(&zC[2][4], a1, (uint32_t)w2, (uint32_t)(w2 >> 32));
            }

            // ---- epilogue 1: gates -> h_tilde, write HT ----
            const float bxi0 = smf[F(OFF_BX) + (l*3 + 0)*128 + kbase];
            const float bxi1 = smf[F(OFF_BX) + (l*3 + 0)*128 + kbase + 1];
            const float bxo0 = smf[F(OFF_BX) + (l*3 + 1)*128 + kbase];
            const float bxo1 = smf[F(OFF_BX) + (l*3 + 1)*128 + kbase + 1];
            const float bxc0 = smf[F(OFF_BX) + (l*3 + 2)*128 + kbase];
            const float bxc1 = smf[F(OFF_BX) + (l*3 + 2)*128 + kbase + 1];
            float ot[8], htl[8];
            #pragma unroll
            for (int mt = 0; mt < 2; mt++) {
                float hts[4];
                #pragma unroll
                for (int rr = 0; rr < 4; rr++) {
                    int idx = mt*4 + rr;
                    bool k1 = rr & 1;
                    float zi = zC[0][idx] + (k1 ? bxi1 : bxi0);
                    float zo = zC[1][idx] + (k1 ? bxo1 : bxo0);
                    float zc = zC[2][idx] + (k1 ? bxc1 : bxc0);
                    float it = sig_f(zi);
                    ot[idx]  = sig_f(zo);
                    htl[idx] = tanh_f(zc) + it;
                    hts[rr]  = htl[idx];
                }
                int row0 = g4 + mt*16, row1 = row0 + 8;
                *(uint32_t*)(sm + OFF_HT + row0*HSTR + kbase*2) = packh2(hts[0], hts[1]);
                *(uint32_t*)(sm + OFF_HT + row1*HSTR + kbase*2) = packh2(hts[2], hts[3]);
            }
            __syncthreads();

            // ---- Wd GEMM: M=32, n-tile w, K=128 ----
            float zD[8];
            #pragma unroll
            for (int i = 0; i < 8; i++) zD[i] = 0.0f;
            const ull* wbW = g_wb + (size_t)l * 4096 + w*32 + lane;
            ull wd = wbW[0];
            #pragma unroll 4
            for (int kt = 0; kt < 8; kt++) {
                uint32_t h0[4], h1[4];
                ldm4(h0, smb + OFF_HT + lmH0 + kt*32);
                ldm4(h1, smb + OFF_HT + lmH1 + kt*32);
                ull wv = wd;
                if (kt < 7) wd = wbW[(kt + 1) * 512];
                mma16816(&zD[0], h0, (uint32_t)wv, (uint32_t)(wv >> 32));
                mma16816(&zD[4], h1, (uint32_t)wv, (uint32_t)(wv >> 32));
            }

            // ---- epilogue 2: recurrence, state update, write h operand ----
            const float bd0 = smf[F(OFF_BD) + l*128 + kbase];
            const float bd1 = smf[F(OFF_BD) + l*128 + kbase + 1];
            const float wt0 = smf[F(OFF_WT) + l*128 + kbase];
            const float wt1 = smf[F(OFF_WT) + l*128 + kbase + 1];
            const float bt0 = smf[F(OFF_BT) + l*128 + kbase];
            const float bt1 = smf[F(OFF_BT) + l*128 + kbase + 1];
            float dec4[4], msk4[4];
            int lst4[4];
            #pragma unroll
            for (int q = 0; q < 4; q++) {
                int row = g4 + q*8;   // q = mt*2 + (rr>>1)
                dec4[q] = smf[F(OFF_DEC) + row];
                msk4[q] = smf[F(OFF_MSK) + row];
                lst4[q] = lastArr[row];
            }
            #pragma unroll
            for (int mt = 0; mt < 2; mt++) {
                float hvv[4];
                #pragma unroll
                for (int rr = 0; rr < 4; rr++) {
                    int idx = mt*4 + rr;
                    int q   = mt*2 + (rr >> 1);
                    bool k1 = rr & 1;
                    float hs    = tanh_f(zD[idx] + (k1 ? bd1 : bd0));
                    float dt    = sig_f(dec4[q] * (k1 ? wt1 : wt0) + (k1 ? bt1 : bt0));
                    float hstar = (htl[idx] - hs) + hs * dt;
                    float cold  = cS[l][idx];
                    float cn    = tanh_f(hstar + ot[idx] * cold);
                    float hn    = ot[idx] * tanh_f(cn);
                    float m     = msk4[q];
                    float hv    = m * hn + (1.0f - m) * hS[l][idx];
                    float cv    = m * cn + (1.0f - m) * cold;
                    cS[l][idx] = cv;
                    hS[l][idx] = hv;
                    hvv[rr] = hv;
                    if (l == 1 && t == lst4[q])
                        smf[F(OFF_SV) + (g4 + q*8)*128 + kbase + (rr & 1)] = m * hv;
                }
                uint32_t p01 = packh2(hvv[0], hvv[1]);
                uint32_t p23 = packh2(hvv[2], hvv[3]);
                int row0 = g4 + mt*16, row1 = row0 + 8;
                if (l == 0) {
                    *(uint32_t*)(sm + OFF_A1 + row0*ASTR + kbase*2) = p01;
                    *(uint32_t*)(sm + OFF_A1 + row1*ASTR + kbase*2) = p23;
                    *(uint32_t*)(sm + OFF_A0 + row0*ASTR + 256 + kbase*2) = p01;
                    *(uint32_t*)(sm + OFF_A0 + row1*ASTR + 256 + kbase*2) = p23;
                } else {
                    *(uint32_t*)(sm + OFF_A1 + row0*ASTR + 256 + kbase*2) = p01;
                    *(uint32_t*)(sm + OFF_A1 + row1*ASTR + 256 + kbase*2) = p23;
                }
            }
            __syncthreads();
        }
    }

    // ================= forecast head =================
    {
        int r = tid >> 4, d = tid & 15;
        smf[F(OFF_HISTB) + r*16 + d] =
            history[((size_t)(b0 + r) * Lh + lastArr[r]) * Dh + d];
    }
    __syncthreads();

    const unsigned FULL = 0xffffffffu;
    #pragma unroll
    for (int rr = 0; rr < 2; rr++) {
        const int r = w * 2 + rr;

        float s = 0.0f, s2 = 0.0f;
        for (int i = lane; i < HEAD_IN; i += 32) {
            float v = (i < 16) ? smf[F(OFF_HISTB) + r*16 + i]
                               : smf[F(OFF_SV) + r*128 + (i - 16)];
            s += v; s2 += v * v;
        }
        #pragma unroll
        for (int off = 16; off; off >>= 1) {
            s  += __shfl_xor_sync(FULL, s,  off);
            s2 += __shfl_xor_sync(FULL, s2, off);
        }
        float mean = s / (float)HEAD_IN;
        float var  = s2 / (float)HEAD_IN - mean * mean;
        float rstd = rsqrtf(var + 1e-5f);

        const int j0 = lane * 4;
        float4 acc = *reinterpret_cast<const float4*>(b1 + j0);
        for (int i = 0; i < HEAD_IN; i++) {
            float v  = (i < 16) ? smf[F(OFF_HISTB) + r*16 + i]
                                : smf[F(OFF_SV) + r*128 + (i - 16)];
            float sn = (v - mean) * rstd * ln_g[i] + ln_b[i];
            float4 w4 = *reinterpret_cast<const float4*>(W1 + i * Hh + j0);
            acc.x += sn * w4.x; acc.y += sn * w4.y;
            acc.z += sn * w4.z; acc.w += sn * w4.w;
        }
        float y[4] = { fmaxf(acc.x, 0.0f), fmaxf(acc.y, 0.0f),
                       fmaxf(acc.z, 0.0f), fmaxf(acc.w, 0.0f) };

        const int o0 = lane, o1 = lane + 32;
        float a0 = b2[o0];
        float a1 = (o1 < OUTD) ? b2[o1] : 0.0f;
        #pragma unroll
        for (int q = 0; q < 4; q++) {
            float yq = y[q];
            #pragma unroll 8
            for (int src = 0; src < 32; src++) {
                float v = __shfl_sync(FULL, yq, src);
                int   j = src * 4 + q;
                a0 += v * W2[j * OUTD + o0];
                if (o1 < OUTD) a1 += v * W2[j * OUTD + o1];
            }
        }
        size_t ob = (size_t)(b0 + r) * OUTD;
        out[ob + o0] = fixv(a0);
        if (o1 < OUTD) out[ob + o1] = fixv(a1);
    }
}

extern "C" void kernel_launch(void* const* d_in, const int* in_sizes, int n_in,
                              void* d_out, int out_size)
{
    const float* history = (const float*)d_in[0];
    const float* hmask   = (const float*)d_in[1];
    const float* Wp      = (const float*)d_in[2];
    const float* bp      = (const float*)d_in[3];
    const float* Wx      = (const float*)d_in[4];
    const float* bx      = (const float*)d_in[5];
    const float* Uh      = (const float*)d_in[6];
    const float* Wd      = (const float*)d_in[7];
    const float* bd      = (const float*)d_in[8];
    const float* Wt      = (const float*)d_in[9];
    const float* bt      = (const float*)d_in[10];
    const float* ln_g    = (const float*)d_in[11];
    const float* ln_b    = (const float*)d_in[12];
    const float* W1      = (const float*)d_in[13];
    const float* b1      = (const float*)d_in[14];
    const float* W2      = (const float*)d_in[15];
    const float* b2      = (const float*)d_in[16];

    pack_kernel<<<225, 256>>>(Wx, Uh, Wd);

    cudaFuncSetAttribute(tlstm_mma_kernel,
                         cudaFuncAttributeMaxDynamicSharedMemorySize, SMEM_TOTAL);
    tlstm_mma_kernel<<<CTAS, THREADS, SMEM_TOTAL>>>(
        history, hmask, Wp, bp, bx, bd, Wt, bt,
        ln_g, ln_b, W1, b1, W2, b2, (float*)d_out);
}